// round 5
// baseline (speedup 1.0000x reference)
#include <cuda_runtime.h>
#include <cuda_bf16.h>
#include <cstdint>
#include <cstddef>

// ---------------- problem constants (fixed shapes) ----------------
#define NB 8
#define NQ 300
#define NM 100
#define NCLS 81
#define HW 16384
#define MPAD 128           // gt padded to 128 for N dim (row 100 = ones)
#define KSPLIT 4
#define KLEN (HW / KSPLIT) // 4096 elems per K-split
#define BK 64              // K tile = 128B bf16 row
#define KT (KLEN / BK)     // 64 iterations

// ---------------- static device scratch (no allocations allowed) ----------------
__device__ __nv_bfloat16 g_GM[(size_t)NB * MPAD * HW];   // gt_masks bf16 (+ ones row 100)
__device__ float g_NUM[(size_t)KSPLIT * NB * NQ * NM];   // partial dot products
__device__ float g_PSUM[(size_t)KSPLIT * NB * NQ];       // partial pm row sums (ones col)
__device__ float g_gm_sum[NB * NM];

// ===================== kernel 1: gt -> bf16 convert + row sums + ones row =====================
__global__ void __launch_bounds__(256) k_convert_gt(const float* __restrict__ gm) {
    int bm = blockIdx.x;                       // 0..(NB*101-1)
    int b = bm / (NM + 1), m = bm - b * (NM + 1);
    uint32_t* dst = reinterpret_cast<uint32_t*>(g_GM + ((size_t)b * MPAD + m) * HW);
    if (m == NM) {                             // ones row (index 100)
        for (int i = threadIdx.x; i < HW / 2; i += 256) dst[i] = 0x3F803F80u;
        return;
    }
    const float4* src = reinterpret_cast<const float4*>(gm + ((size_t)b * NM + m) * HW);
    float sum = 0.f;
    for (int i = threadIdx.x; i < HW / 4; i += 256) {
        float4 v = src[i];
        sum += (v.x + v.y) + (v.z + v.w);
        __nv_bfloat162 lo = __floats2bfloat162_rn(v.x, v.y);
        __nv_bfloat162 hi = __floats2bfloat162_rn(v.z, v.w);
        dst[2 * i]     = *reinterpret_cast<uint32_t*>(&lo);
        dst[2 * i + 1] = *reinterpret_cast<uint32_t*>(&hi);
    }
    for (int o = 16; o; o >>= 1) sum += __shfl_down_sync(0xffffffffu, sum, o);
    __shared__ float ws[8];
    if ((threadIdx.x & 31) == 0) ws[threadIdx.x >> 5] = sum;
    __syncthreads();
    if (threadIdx.x == 0) {
        float t = 0.f;
        #pragma unroll
        for (int w = 0; w < 8; ++w) t += ws[w];
        g_gm_sum[b * NM + m] = t;
    }
}

// ===================== kernel 2: fused sigmoid + mma.sync bf16 GEMM =====================
#define TILE_BYTES 16384          // 128 rows x 128B bf16
#define GEMM_SMEM (4 * TILE_BYTES)

__device__ __forceinline__ uint32_t sw128(uint32_t off) {
    return off ^ ((off >> 3) & 0x70);
}

__device__ __forceinline__ void cp_tileB(const __nv_bfloat16* __restrict__ src,
                                         uint32_t dstBase) {
    int t = threadIdx.x;
    #pragma unroll
    for (int s = 0; s < 4; ++s) {
        int i = t + s * 256;                  // 0..1023
        int row = i >> 3, c16 = i & 7;
        unsigned long long g =
            __cvta_generic_to_global(src + (size_t)row * HW + c16 * 8);
        uint32_t off = sw128((uint32_t)(row * 128 + c16 * 16));
        asm volatile("cp.async.cg.shared.global [%0], [%1], 16;"
                     :: "r"(dstBase + off), "l"(g));
    }
}

__global__ void __launch_bounds__(256) k_mask_gemm(const float* __restrict__ pm) {
    extern __shared__ char smem[];
    uint32_t sA = (uint32_t)__cvta_generic_to_shared(smem);  // 2 x 16KB bf16 A
    uint32_t sB = sA + 2 * TILE_BYTES;                       // 2 x 16KB bf16 B

    int tid = threadIdx.x, lane = tid & 31, warp = tid >> 5;
    int wm = warp & 1, wn = warp >> 1;        // 2 x 4 warp grid
    int warpRow = wm * 64, warpCol = wn * 32;

    int tile = blockIdx.x, b = blockIdx.y, ks = blockIdx.z;
    int q0 = tile * 128;

    // ---- A source pointers: 8 rows per thread (row = rowc + s*16), clamped ----
    int rowc = tid >> 4;                      // 0..15
    int kc = tid & 15;                        // 16B column group within 64-elem row
    const float4* aptr[8];
    #pragma unroll
    for (int s = 0; s < 8; ++s) {
        int q = q0 + rowc + s * 16;
        if (q > NQ - 1) q = NQ - 1;           // clamp padding rows (discarded)
        aptr[s] = reinterpret_cast<const float4*>(
            pm + ((size_t)b * NQ + q) * HW + (size_t)ks * KLEN + kc * 4);
    }
    const __nv_bfloat16* Bbase = g_GM + (size_t)b * MPAD * HW + (size_t)ks * KLEN;

    float acc[4][4][4];
    #pragma unroll
    for (int i = 0; i < 4; ++i)
        #pragma unroll
        for (int j = 0; j < 4; ++j)
            #pragma unroll
            for (int r = 0; r < 4; ++r) acc[i][j][r] = 0.f;

    float4 pf[8];
    // prologue: A iter 0 regs, B iter 0 cp.async
    #pragma unroll
    for (int s = 0; s < 8; ++s) pf[s] = aptr[s][0];
    cp_tileB(Bbase, sB);
    asm volatile("cp.async.commit_group;");
    // convert + store A iter 0 into buffer 0
    {
        char* base = smem;                    // A buffer 0
        #pragma unroll
        for (int s = 0; s < 8; ++s) {
            int row = rowc + s * 16;
            float4 v = pf[s];
            float s0 = 1.f / (1.f + __expf(-v.x));
            float s1 = 1.f / (1.f + __expf(-v.y));
            float s2 = 1.f / (1.f + __expf(-v.z));
            float s3 = 1.f / (1.f + __expf(-v.w));
            __nv_bfloat162 lo = __floats2bfloat162_rn(s0, s1);
            __nv_bfloat162 hi = __floats2bfloat162_rn(s2, s3);
            uint2 w = make_uint2(*reinterpret_cast<uint32_t*>(&lo),
                                 *reinterpret_cast<uint32_t*>(&hi));
            uint32_t off = sw128((uint32_t)(row * 128 + kc * 8));
            *reinterpret_cast<uint2*>(base + off) = w;
        }
    }
    asm volatile("cp.async.wait_group 0;");
    __syncthreads();

    int rA = warpRow + (lane & 15);
    int cAsel = lane >> 4;
    int rB = warpCol + (lane & 7);
    int cBsel = (lane >> 3) & 1;

    int st = 0;
    for (int kt = 0; kt < KT; ++kt) {
        int nst = st ^ 1;
        if (kt + 1 < KT) {
            // prefetch A regs and B tile for next iteration
            #pragma unroll
            for (int s = 0; s < 8; ++s) pf[s] = aptr[s][(kt + 1) * 16];
            cp_tileB(Bbase + (size_t)(kt + 1) * BK, sB + nst * TILE_BYTES);
            asm volatile("cp.async.commit_group;");
        }
        uint32_t a0 = sA + st * TILE_BYTES;
        uint32_t b0 = sB + st * TILE_BYTES;

        #pragma unroll
        for (int kk = 0; kk < 4; ++kk) {
            uint32_t af[4][4], bf[4][2];
            #pragma unroll
            for (int mt = 0; mt < 4; ++mt) {
                uint32_t addr = a0 + sw128((uint32_t)((rA + mt * 16) * 128
                                                      + (kk * 2 + cAsel) * 16));
                asm volatile("ldmatrix.sync.aligned.m8n8.x4.shared.b16 "
                             "{%0,%1,%2,%3}, [%4];"
                             : "=r"(af[mt][0]), "=r"(af[mt][1]),
                               "=r"(af[mt][2]), "=r"(af[mt][3]) : "r"(addr));
            }
            #pragma unroll
            for (int nt = 0; nt < 4; ++nt) {
                uint32_t addr = b0 + sw128((uint32_t)((rB + nt * 8) * 128
                                                      + (kk * 2 + cBsel) * 16));
                asm volatile("ldmatrix.sync.aligned.m8n8.x2.shared.b16 "
                             "{%0,%1}, [%2];"
                             : "=r"(bf[nt][0]), "=r"(bf[nt][1]) : "r"(addr));
            }
            #pragma unroll
            for (int mt = 0; mt < 4; ++mt)
                #pragma unroll
                for (int nt = 0; nt < 4; ++nt) {
                    asm volatile(
                        "mma.sync.aligned.m16n8k16.row.col.f32.bf16.bf16.f32 "
                        "{%0,%1,%2,%3}, {%4,%5,%6,%7}, {%8,%9}, {%0,%1,%2,%3};"
                        : "+f"(acc[mt][nt][0]), "+f"(acc[mt][nt][1]),
                          "+f"(acc[mt][nt][2]), "+f"(acc[mt][nt][3])
                        : "r"(af[mt][0]), "r"(af[mt][1]),
                          "r"(af[mt][2]), "r"(af[mt][3]),
                          "r"(bf[nt][0]), "r"(bf[nt][1]));
                }
        }

        if (kt + 1 < KT) {
            // convert prefetched A regs into the other buffer
            char* base = smem + nst * TILE_BYTES;
            #pragma unroll
            for (int s = 0; s < 8; ++s) {
                int row = rowc + s * 16;
                float4 v = pf[s];
                float s0 = 1.f / (1.f + __expf(-v.x));
                float s1 = 1.f / (1.f + __expf(-v.y));
                float s2 = 1.f / (1.f + __expf(-v.z));
                float s3 = 1.f / (1.f + __expf(-v.w));
                __nv_bfloat162 lo = __floats2bfloat162_rn(s0, s1);
                __nv_bfloat162 hi = __floats2bfloat162_rn(s2, s3);
                uint2 w = make_uint2(*reinterpret_cast<uint32_t*>(&lo),
                                     *reinterpret_cast<uint32_t*>(&hi));
                uint32_t off = sw128((uint32_t)(row * 128 + kc * 8));
                *reinterpret_cast<uint2*>(base + off) = w;
            }
            asm volatile("cp.async.wait_group 0;");
        }
        __syncthreads();
        st = nst;
    }

    // epilogue: m<100 -> g_NUM; m==100 (ones column) -> g_PSUM
    float* dst = g_NUM + ((size_t)ks * NB + b) * NQ * NM;
    float* psd = g_PSUM + ((size_t)ks * NB + b) * NQ;
    int rowInTile = lane >> 2;
    int colInTile = (lane & 3) * 2;
    #pragma unroll
    for (int mt = 0; mt < 4; ++mt) {
        #pragma unroll
        for (int nt = 0; nt < 4; ++nt) {
            int qb = q0 + warpRow + mt * 16 + rowInTile;
            int mb = warpCol + nt * 8 + colInTile;
            #pragma unroll
            for (int r = 0; r < 4; ++r) {
                int q = qb + ((r >> 1) ? 8 : 0);
                int m = mb + (r & 1);
                if (q < NQ) {
                    if (m < NM) dst[(size_t)q * NM + m] = acc[mt][nt][r];
                    else if (m == NM) psd[q] = acc[mt][nt][r];
                }
            }
        }
    }
}

// ===================== kernel 3: assemble full cost matrix =====================
__global__ void __launch_bounds__(128) k_finalize(const float* __restrict__ logits,
                                                  const float* __restrict__ pboxes,
                                                  const int* __restrict__ glabels,
                                                  const float* __restrict__ gboxes,
                                                  float* __restrict__ out) {
    int q = blockIdx.x, b = blockIdx.y;
    int tid = threadIdx.x;
    __shared__ float probs[NCLS];
    __shared__ float red[128];

    const float* lg = logits + ((size_t)b * NQ + q) * NCLS;
    float x = (tid < NCLS) ? lg[tid] : -3.0e38f;
    red[tid] = x; __syncthreads();
    #pragma unroll
    for (int s = 64; s > 0; s >>= 1) { if (tid < s) red[tid] = fmaxf(red[tid], red[tid + s]); __syncthreads(); }
    float mx = red[0]; __syncthreads();
    float e = (tid < NCLS) ? __expf(x - mx) : 0.f;
    red[tid] = e; __syncthreads();
    #pragma unroll
    for (int s = 64; s > 0; s >>= 1) { if (tid < s) red[tid] += red[tid + s]; __syncthreads(); }
    float inv = 1.f / red[0];
    if (tid < NCLS) probs[tid] = e * inv;
    __syncthreads();

    const float* pb = pboxes + ((size_t)b * NQ + q) * 4;
    float px1 = pb[0], py1 = pb[1], px2 = pb[2], py2 = pb[3];
    float pa = (px2 - px1) * (py2 - py1);
    float psum = g_PSUM[(0 * NB + b) * NQ + q] + g_PSUM[(1 * NB + b) * NQ + q]
               + g_PSUM[(2 * NB + b) * NQ + q] + g_PSUM[(3 * NB + b) * NQ + q];
    const size_t NSTR = (size_t)NB * NQ * NM;

    for (int m = tid; m < NM; m += 128) {
        int lbl = glabels[b * NM + m];
        float cclass = -probs[lbl];
        const float* gb = gboxes + ((size_t)b * NM + m) * 4;
        float gx1 = gb[0], gy1 = gb[1], gx2 = gb[2], gy2 = gb[3];
        float l1 = fabsf(px1 - gx1) + fabsf(py1 - gy1) + fabsf(px2 - gx2) + fabsf(py2 - gy2);
        float iw = fmaxf(fminf(px2, gx2) - fmaxf(px1, gx1), 0.f);
        float ih = fmaxf(fminf(py2, gy2) - fmaxf(py1, gy1), 0.f);
        float inter = iw * ih;
        float ga = (gx2 - gx1) * (gy2 - gy1);
        float uni = pa + ga - inter;
        float iou = inter / (uni + 1e-6f);
        float ew = fmaxf(fmaxf(px2, gx2) - fminf(px1, gx1), 0.f);
        float eh = fmaxf(fmaxf(py2, gy2) - fminf(py1, gy1), 0.f);
        float am = ew * eh;
        float giou = iou - (am - uni) / (am + 1e-6f);
        size_t ni = ((size_t)b * NQ + q) * NM + m;
        float dot = g_NUM[ni] + g_NUM[NSTR + ni] + g_NUM[2 * NSTR + ni] + g_NUM[3 * NSTR + ni];
        float den = psum + g_gm_sum[b * NM + m];
        float cmask = 1.f - (2.f * dot) / (den + 1e-6f);
        out[ni] = cclass + 5.f * (l1 - giou) + 2.f * cmask;
    }
}

// ===================== kernel 4: single-warp JV, f32 + redux argmin =====================
#define HUNG_THREADS 512
#define HUNG_SMEM (NM * 4 + NM * NQ * 4 + NQ * 4 * 2 + NM * 4)
#define NSLOT 10

__device__ __forceinline__ uint32_t fkey(float f) {
    uint32_t u = __float_as_uint(f);
    return (u & 0x80000000u) ? ~u : (u | 0x80000000u);
}
__device__ __forceinline__ float funkey(uint32_t k) {
    uint32_t u = (k & 0x80000000u) ? (k & 0x7fffffffu) : ~k;
    return __uint_as_float(u);
}
__device__ __forceinline__ uint32_t redux_min(uint32_t v) {
    uint32_t d;
    asm volatile("redux.sync.min.u32 %0, %1, 0xffffffff;" : "=r"(d) : "r"(v));
    return d;
}

__global__ void __launch_bounds__(HUNG_THREADS) k_hungarian(float* __restrict__ out, int out_size) {
    extern __shared__ char sm[];
    float* u    = reinterpret_cast<float*>(sm);               // [100]
    float* cost = u + NM;                                     // [100][300]
    int* p      = reinterpret_cast<int*>(cost + NM * NQ);     // [300]
    int* way    = p + NQ;                                     // [300]
    int* rowdone = way + NQ;                                  // [100]

    int b = blockIdx.x;
    int tid = threadIdx.x;
    const float* C = out + (size_t)b * NQ * NM;

    for (int idx = tid; idx < NM * NQ; idx += HUNG_THREADS) {
        int q = idx / NM, m = idx - q * NM;
        cost[m * NQ + q] = C[idx];
    }
    for (int j = tid; j < NQ; j += HUNG_THREADS) p[j] = -1;
    __syncthreads();
    if (tid >= 32) return;

    const int lane = tid;
    const bool valid9 = (lane < 12);          // col 288..299 only

    float vv[NSLOT], minv[NSLOT];
    #pragma unroll
    for (int s = 0; s < NSLOT; ++s) vv[s] = 0.0f;

    // ---- row reduction + greedy seed ----
    for (int i = 0; i < NM; ++i) {
        const float* crow = cost + i * NQ;
        uint32_t bk = 0xffffffffu; int bi = 0x7fffffff;
        #pragma unroll
        for (int s = 0; s < NSLOT; ++s) {
            int col = s * 32 + lane;
            if (s < 9 || valid9) {
                uint32_t k = fkey(crow[col]);
                if (k < bk) { bk = k; bi = col; }
            }
        }
        uint32_t mk = redux_min(bk);
        uint32_t cand = (bk == mk) ? (uint32_t)bi : 0xffffffffu;
        uint32_t jstar = redux_min(cand);
        if (lane == 0) {
            u[i] = funkey(mk);
            if (p[jstar] == -1) { p[jstar] = i; rowdone[i] = 1; }
            else rowdone[i] = 0;
        }
    }
    __syncwarp();

    // ---- augment remaining rows ----
    for (int i = 0; i < NM; ++i) {
        if (rowdone[i]) continue;
        unsigned usedmask = 0;
        #pragma unroll
        for (int s = 0; s < NSLOT; ++s) minv[s] = 3.0e38f;
        int cr = i, j0 = -1;

        while (true) {
            float ucr = u[cr];
            const float* crow = cost + cr * NQ;
            uint32_t bk = 0xffffffffu; int bi = 0x7fffffff;
            #pragma unroll
            for (int s = 0; s < NSLOT; ++s) {
                int col = s * 32 + lane;
                bool ok = (s < 9 || valid9) && !((usedmask >> s) & 1u);
                if (ok) {
                    float cur = crow[col] - ucr - vv[s];
                    if (cur < minv[s]) { minv[s] = cur; way[col] = j0; }
                    uint32_t k = fkey(minv[s]);
                    if (k < bk) { bk = k; bi = col; }
                }
            }
            uint32_t mk = redux_min(bk);
            float delta = funkey(mk);
            uint32_t cand = (bk == mk) ? (uint32_t)bi : 0xffffffffu;
            int j1 = (int)redux_min(cand);

            #pragma unroll
            for (int s = 0; s < NSLOT; ++s) {
                int col = s * 32 + lane;
                if (s < 9 || valid9) {
                    if ((usedmask >> s) & 1u) {
                        u[p[col]] += delta;
                        vv[s] -= delta;
                    } else {
                        minv[s] -= delta;
                    }
                }
            }
            if (lane == 0) u[i] += delta;
            __syncwarp();

            if (lane == (j1 & 31)) usedmask |= 1u << (j1 >> 5);
            j0 = j1;
            cr = p[j1];
            if (cr == -1) break;
            __syncwarp();
        }

        __syncwarp();
        if (lane == 0) {
            int j = j0;
            while (j != -1) {
                int jp = way[j];
                p[j] = (jp != -1) ? p[jp] : i;
                j = jp;
            }
        }
        __syncwarp();
    }

    if (lane == 0 && out_size >= NB * NQ * NM + 2 * NB * NM) {
        float* pi = out + (size_t)NB * NQ * NM + (size_t)b * NM;
        float* gi = pi + (size_t)NB * NM;
        int r = 0;
        for (int j = 0; j < NQ; ++j)
            if (p[j] >= 0) { pi[r] = (float)j; gi[r] = (float)p[j]; ++r; }
    }
}

// ===================== launch =====================
extern "C" void kernel_launch(void* const* d_in, const int* in_sizes, int n_in,
                              void* d_out, int out_size) {
    const float* pred_logits = (const float*)d_in[0];
    const float* pred_boxes  = (const float*)d_in[1];
    const float* pred_masks  = (const float*)d_in[2];
    const int*   gt_labels   = (const int*)d_in[3];
    const float* gt_boxes    = (const float*)d_in[4];
    const float* gt_masks    = (const float*)d_in[5];
    float* out = (float*)d_out;

    k_convert_gt<<<NB * (NM + 1), 256>>>(gt_masks);

    cudaFuncSetAttribute(k_mask_gemm, cudaFuncAttributeMaxDynamicSharedMemorySize, GEMM_SMEM);
    k_mask_gemm<<<dim3(3, NB, KSPLIT), 256, GEMM_SMEM>>>(pred_masks);

    k_finalize<<<dim3(NQ, NB), 128>>>(pred_logits, pred_boxes, gt_labels, gt_boxes, out);

    cudaFuncSetAttribute(k_hungarian, cudaFuncAttributeMaxDynamicSharedMemorySize, HUNG_SMEM);
    k_hungarian<<<NB, HUNG_THREADS, HUNG_SMEM>>>(out, out_size);
}

// round 6
// speedup vs baseline: 1.8042x; 1.8042x over previous
#include <cuda_runtime.h>
#include <cuda_bf16.h>
#include <cstdint>
#include <cstddef>

// ---------------- problem constants (fixed shapes) ----------------
#define NB 8
#define NQ 300
#define NM 100
#define NCLS 81
#define HW 16384
#define QPAD 384           // 3 tiles of 128 queries
#define MPAD 128           // gt padded to 128 for N dim
#define KSPLIT 4
#define KLEN (HW / KSPLIT) // 4096 bf16 per K-split
#define BK 64              // K tile (bf16 elems) = 128B row
#define KT (KLEN / BK)     // 64 iterations

// ---------------- static device scratch (no allocations allowed) ----------------
__device__ __nv_bfloat16 g_PM[(size_t)NB * QPAD * HW];   // sigmoid(pred_masks), bf16
__device__ __nv_bfloat16 g_GM[(size_t)NB * MPAD * HW];   // gt_masks, bf16
__device__ float g_NUM[(size_t)KSPLIT * NB * NQ * NM];   // partial dot products
__device__ float g_pm_sum[NB * NQ];
__device__ float g_gm_sum[NB * NM];

// ===================== kernel 1: sigmoid + bf16 convert + row sums =====================
__global__ void __launch_bounds__(256) k_convert_pred(const float* __restrict__ pm) {
    int bq = blockIdx.x;                       // 0..2399
    int b = bq / NQ, q = bq - b * NQ;
    const float4* src = reinterpret_cast<const float4*>(pm + (size_t)bq * HW);
    __nv_bfloat162* dst =
        reinterpret_cast<__nv_bfloat162*>(g_PM + ((size_t)b * QPAD + q) * HW);
    float sum = 0.f;
    for (int i = threadIdx.x; i < HW / 4; i += 256) {
        float4 v = src[i];
        float s0 = 1.f / (1.f + __expf(-v.x));
        float s1 = 1.f / (1.f + __expf(-v.y));
        float s2 = 1.f / (1.f + __expf(-v.z));
        float s3 = 1.f / (1.f + __expf(-v.w));
        sum += (s0 + s1) + (s2 + s3);
        dst[2 * i]     = __floats2bfloat162_rn(s0, s1);
        dst[2 * i + 1] = __floats2bfloat162_rn(s2, s3);
    }
    for (int o = 16; o; o >>= 1) sum += __shfl_down_sync(0xffffffffu, sum, o);
    __shared__ float ws[8];
    if ((threadIdx.x & 31) == 0) ws[threadIdx.x >> 5] = sum;
    __syncthreads();
    if (threadIdx.x == 0) {
        float t = 0.f;
        #pragma unroll
        for (int w = 0; w < 8; ++w) t += ws[w];
        g_pm_sum[bq] = t;
    }
}

__global__ void __launch_bounds__(256) k_convert_gt(const float* __restrict__ gm) {
    int bm = blockIdx.x;                       // 0..799
    int b = bm / NM, m = bm - b * NM;
    const float4* src = reinterpret_cast<const float4*>(gm + (size_t)bm * HW);
    __nv_bfloat162* dst =
        reinterpret_cast<__nv_bfloat162*>(g_GM + ((size_t)b * MPAD + m) * HW);
    float sum = 0.f;
    for (int i = threadIdx.x; i < HW / 4; i += 256) {
        float4 v = src[i];
        sum += (v.x + v.y) + (v.z + v.w);
        dst[2 * i]     = __floats2bfloat162_rn(v.x, v.y);
        dst[2 * i + 1] = __floats2bfloat162_rn(v.z, v.w);
    }
    for (int o = 16; o; o >>= 1) sum += __shfl_down_sync(0xffffffffu, sum, o);
    __shared__ float ws[8];
    if ((threadIdx.x & 31) == 0) ws[threadIdx.x >> 5] = sum;
    __syncthreads();
    if (threadIdx.x == 0) {
        float t = 0.f;
        #pragma unroll
        for (int w = 0; w < 8; ++w) t += ws[w];
        g_gm_sum[bm] = t;
    }
}

// ===================== kernel 2: mma.sync bf16 GEMM (dice numerator) =====================
#define TILE_BYTES 16384          // 128 rows x 128B
#define GEMM_SMEM (4 * TILE_BYTES)

__device__ __forceinline__ uint32_t sw128(uint32_t off) {
    return off ^ ((off >> 3) & 0x70);
}

__device__ __forceinline__ void cp_tile(const __nv_bfloat16* __restrict__ src,
                                        uint32_t dstBase) {
    int t = threadIdx.x;
    #pragma unroll
    for (int s = 0; s < 4; ++s) {
        int i = t + s * 256;                  // 0..1023
        int row = i >> 3, c16 = i & 7;
        unsigned long long g =
            __cvta_generic_to_global(src + (size_t)row * HW + c16 * 8);
        uint32_t off = sw128((uint32_t)(row * 128 + c16 * 16));
        asm volatile("cp.async.cg.shared.global [%0], [%1], 16;"
                     :: "r"(dstBase + off), "l"(g));
    }
}

__global__ void __launch_bounds__(256) k_mask_gemm() {
    extern __shared__ char smem[];
    uint32_t sA = (uint32_t)__cvta_generic_to_shared(smem);
    uint32_t sB = sA + 2 * TILE_BYTES;

    int tid = threadIdx.x, lane = tid & 31, warp = tid >> 5;
    int wm = warp & 1, wn = warp >> 1;        // 2 x 4 warp grid
    int warpRow = wm * 64, warpCol = wn * 32;

    int tile = blockIdx.x, b = blockIdx.y, ks = blockIdx.z;
    int q0 = tile * 128;

    const __nv_bfloat16* Abase = g_PM + ((size_t)b * QPAD + q0) * HW + (size_t)ks * KLEN;
    const __nv_bfloat16* Bbase = g_GM + (size_t)b * MPAD * HW + (size_t)ks * KLEN;

    float acc[4][4][4];
    #pragma unroll
    for (int i = 0; i < 4; ++i)
        #pragma unroll
        for (int j = 0; j < 4; ++j)
            #pragma unroll
            for (int r = 0; r < 4; ++r) acc[i][j][r] = 0.f;

    cp_tile(Abase, sA);
    cp_tile(Bbase, sB);
    asm volatile("cp.async.commit_group;");
    asm volatile("cp.async.wait_group 0;");
    __syncthreads();

    int rA = warpRow + (lane & 15);
    int cAsel = lane >> 4;
    int rB = warpCol + (lane & 7);
    int cBsel = (lane >> 3) & 1;

    int st = 0;
    for (int kt = 0; kt < KT; ++kt) {
        if (kt + 1 < KT) {
            int nst = st ^ 1;
            cp_tile(Abase + (size_t)(kt + 1) * BK, sA + nst * TILE_BYTES);
            cp_tile(Bbase + (size_t)(kt + 1) * BK, sB + nst * TILE_BYTES);
            asm volatile("cp.async.commit_group;");
        }
        uint32_t a0 = sA + st * TILE_BYTES;
        uint32_t b0 = sB + st * TILE_BYTES;

        #pragma unroll
        for (int kk = 0; kk < 4; ++kk) {
            uint32_t af[4][4], bf[4][2];
            #pragma unroll
            for (int mt = 0; mt < 4; ++mt) {
                uint32_t addr = a0 + sw128((uint32_t)((rA + mt * 16) * 128
                                                      + (kk * 2 + cAsel) * 16));
                asm volatile("ldmatrix.sync.aligned.m8n8.x4.shared.b16 "
                             "{%0,%1,%2,%3}, [%4];"
                             : "=r"(af[mt][0]), "=r"(af[mt][1]),
                               "=r"(af[mt][2]), "=r"(af[mt][3]) : "r"(addr));
            }
            #pragma unroll
            for (int nt = 0; nt < 4; ++nt) {
                uint32_t addr = b0 + sw128((uint32_t)((rB + nt * 8) * 128
                                                      + (kk * 2 + cBsel) * 16));
                asm volatile("ldmatrix.sync.aligned.m8n8.x2.shared.b16 "
                             "{%0,%1}, [%2];"
                             : "=r"(bf[nt][0]), "=r"(bf[nt][1]) : "r"(addr));
            }
            #pragma unroll
            for (int mt = 0; mt < 4; ++mt)
                #pragma unroll
                for (int nt = 0; nt < 4; ++nt) {
                    asm volatile(
                        "mma.sync.aligned.m16n8k16.row.col.f32.bf16.bf16.f32 "
                        "{%0,%1,%2,%3}, {%4,%5,%6,%7}, {%8,%9}, {%0,%1,%2,%3};"
                        : "+f"(acc[mt][nt][0]), "+f"(acc[mt][nt][1]),
                          "+f"(acc[mt][nt][2]), "+f"(acc[mt][nt][3])
                        : "r"(af[mt][0]), "r"(af[mt][1]),
                          "r"(af[mt][2]), "r"(af[mt][3]),
                          "r"(bf[nt][0]), "r"(bf[nt][1]));
                }
        }
        if (kt + 1 < KT) {
            asm volatile("cp.async.wait_group 0;");
        }
        __syncthreads();
        st ^= 1;
    }

    float* dst = g_NUM + ((size_t)ks * NB + b) * NQ * NM;
    int rowInTile = lane >> 2;
    int colInTile = (lane & 3) * 2;
    #pragma unroll
    for (int mt = 0; mt < 4; ++mt) {
        #pragma unroll
        for (int nt = 0; nt < 4; ++nt) {
            int qb = q0 + warpRow + mt * 16 + rowInTile;
            int mb = warpCol + nt * 8 + colInTile;
            #pragma unroll
            for (int r = 0; r < 4; ++r) {
                int q = qb + ((r >> 1) ? 8 : 0);
                int m = mb + (r & 1);
                if (q < NQ && m < NM)
                    dst[(size_t)q * NM + m] = acc[mt][nt][r];
            }
        }
    }
}

// ===================== kernel 3: assemble full cost matrix =====================
__global__ void __launch_bounds__(128) k_finalize(const float* __restrict__ logits,
                                                  const float* __restrict__ pboxes,
                                                  const int* __restrict__ glabels,
                                                  const float* __restrict__ gboxes,
                                                  float* __restrict__ out) {
    int q = blockIdx.x, b = blockIdx.y;
    int tid = threadIdx.x;
    __shared__ float probs[NCLS];
    __shared__ float red[128];

    const float* lg = logits + ((size_t)b * NQ + q) * NCLS;
    float x = (tid < NCLS) ? lg[tid] : -3.0e38f;
    red[tid] = x; __syncthreads();
    #pragma unroll
    for (int s = 64; s > 0; s >>= 1) { if (tid < s) red[tid] = fmaxf(red[tid], red[tid + s]); __syncthreads(); }
    float mx = red[0]; __syncthreads();
    float e = (tid < NCLS) ? __expf(x - mx) : 0.f;
    red[tid] = e; __syncthreads();
    #pragma unroll
    for (int s = 64; s > 0; s >>= 1) { if (tid < s) red[tid] += red[tid + s]; __syncthreads(); }
    float inv = 1.f / red[0];
    if (tid < NCLS) probs[tid] = e * inv;
    __syncthreads();

    const float* pb = pboxes + ((size_t)b * NQ + q) * 4;
    float px1 = pb[0], py1 = pb[1], px2 = pb[2], py2 = pb[3];
    float pa = (px2 - px1) * (py2 - py1);
    float psum = g_pm_sum[b * NQ + q];
    const size_t NSTR = (size_t)NB * NQ * NM;

    for (int m = tid; m < NM; m += 128) {
        int lbl = glabels[b * NM + m];
        float cclass = -probs[lbl];
        const float* gb = gboxes + ((size_t)b * NM + m) * 4;
        float gx1 = gb[0], gy1 = gb[1], gx2 = gb[2], gy2 = gb[3];
        float l1 = fabsf(px1 - gx1) + fabsf(py1 - gy1) + fabsf(px2 - gx2) + fabsf(py2 - gy2);
        float iw = fmaxf(fminf(px2, gx2) - fmaxf(px1, gx1), 0.f);
        float ih = fmaxf(fminf(py2, gy2) - fmaxf(py1, gy1), 0.f);
        float inter = iw * ih;
        float ga = (gx2 - gx1) * (gy2 - gy1);
        float uni = pa + ga - inter;
        float iou = inter / (uni + 1e-6f);
        float ew = fmaxf(fmaxf(px2, gx2) - fminf(px1, gx1), 0.f);
        float eh = fmaxf(fmaxf(py2, gy2) - fminf(py1, gy1), 0.f);
        float am = ew * eh;
        float giou = iou - (am - uni) / (am + 1e-6f);
        size_t ni = ((size_t)b * NQ + q) * NM + m;
        float dot = g_NUM[ni] + g_NUM[NSTR + ni] + g_NUM[2 * NSTR + ni] + g_NUM[3 * NSTR + ni];
        float den = psum + g_gm_sum[b * NM + m];
        float cmask = 1.f - (2.f * dot) / (den + 1e-6f);
        out[ni] = cclass + 5.f * (l1 - giou) + 2.f * cmask;
    }
}

// ===================== kernel 4: single-warp JV + LAPJV augmenting row reduction ==========
#define HUNG_THREADS 512
#define HUNG_SMEM (NM * 4 + NM * NQ * 4 + NQ * 8 + NM * 8)
#define NSLOT 10

__device__ __forceinline__ uint32_t fkey(float f) {
    uint32_t u = __float_as_uint(f);
    return (u & 0x80000000u) ? ~u : (u | 0x80000000u);
}
__device__ __forceinline__ float funkey(uint32_t k) {
    uint32_t u = (k & 0x80000000u) ? (k & 0x7fffffffu) : ~k;
    return __uint_as_float(u);
}
__device__ __forceinline__ uint32_t redux_min(uint32_t v) {
    uint32_t d;
    asm volatile("redux.sync.min.u32 %0, %1, 0xffffffff;" : "=r"(d) : "r"(v));
    return d;
}

__global__ void __launch_bounds__(HUNG_THREADS) k_hungarian(float* __restrict__ out, int out_size) {
    extern __shared__ char sm[];
    float* u    = reinterpret_cast<float*>(sm);               // [100]
    float* cost = u + NM;                                     // [100][300] transposed
    int* p      = reinterpret_cast<int*>(cost + NM * NQ);     // [300]
    int* way    = p + NQ;                                     // [300]
    int* flA    = way + NQ;                                   // [100]
    int* flB    = flA + NM;                                   // [100]

    int b = blockIdx.x;
    int tid = threadIdx.x;
    const float* C = out + (size_t)b * NQ * NM;

    for (int idx = tid; idx < NM * NQ; idx += HUNG_THREADS) {
        int q = idx / NM, m = idx - q * NM;
        cost[m * NQ + q] = C[idx];
    }
    for (int j = tid; j < NQ; j += HUNG_THREADS) p[j] = -1;
    __syncthreads();
    if (tid >= 32) return;

    const int lane = tid;
    const bool valid9 = (lane < 12);          // col 288..299 only

    float vv[NSLOT], minv[NSLOT];
    #pragma unroll
    for (int s = 0; s < NSLOT; ++s) vv[s] = 0.0f;

    // ---- phase 1: row reduction + greedy seed ----
    int nfree = 0;
    for (int i = 0; i < NM; ++i) {
        const float* crow = cost + i * NQ;
        uint32_t bk = 0xffffffffu; int bi = 0x7fffffff;
        #pragma unroll
        for (int s = 0; s < NSLOT; ++s) {
            int col = s * 32 + lane;
            if (s < 9 || valid9) {
                uint32_t k = fkey(crow[col]);
                if (k < bk) { bk = k; bi = col; }
            }
        }
        uint32_t mk = redux_min(bk);
        int jstar = (int)redux_min((bk == mk) ? (uint32_t)bi : 0xffffffffu);
        int pj = p[jstar];                    // broadcast read before write
        __syncwarp();
        if (lane == 0) {
            u[i] = funkey(mk);
            if (pj == -1) p[jstar] = i;
        }
        if (pj != -1) { if (lane == 0) flA[nfree] = i; ++nfree; }
        __syncwarp();
    }

    // ---- phase 2: augmenting row reduction (<=2 passes) ----
    int* cur = flA; int* nxt = flB;
    for (int pass = 0; pass < 2 && nfree > 0; ++pass) {
        int nnew = 0;
        for (int k = 0; k < nfree; ++k) {
            int i = cur[k];
            for (;;) {
                const float* crow = cost + i * NQ;
                uint32_t keys[NSLOT];
                uint32_t bk = 0xffffffffu; int bi = 0x7fffffff;
                #pragma unroll
                for (int s = 0; s < NSLOT; ++s) {
                    int col = s * 32 + lane;
                    uint32_t kk = 0xffffffffu;
                    if (s < 9 || valid9) kk = fkey(crow[col] - vv[s]);
                    keys[s] = kk;
                    if (kk < bk) { bk = kk; bi = col; }
                }
                uint32_t u1k = redux_min(bk);
                int j1 = (int)redux_min((bk == u1k) ? (uint32_t)bi : 0xffffffffu);
                // second min (exclude column j1)
                uint32_t bk2 = 0xffffffffu; int bi2 = 0x7fffffff;
                #pragma unroll
                for (int s = 0; s < NSLOT; ++s) {
                    int col = s * 32 + lane;
                    if (col != j1 && keys[s] < bk2) { bk2 = keys[s]; bi2 = col; }
                }
                uint32_t u2k = redux_min(bk2);
                int j2 = (int)redux_min((bk2 == u2k) ? (uint32_t)bi2 : 0xffffffffu);

                float u1 = funkey(u1k), u2 = funkey(u2k);
                bool strict = (u1 < u2);
                int jt = j1;
                if (!strict) {
                    int pj1 = p[j1], pj2 = p[j2];
                    if (pj1 != -1 && pj2 == -1) jt = j2;
                }
                __syncwarp();
                int ev = p[jt];               // broadcast read
                __syncwarp();
                if (lane == 0) { u[i] = u2; p[jt] = i; }
                if (strict && lane == (jt & 31)) vv[jt >> 5] -= (u2 - u1);
                __syncwarp();

                if (ev == -1) break;
                if (strict) { i = ev; continue; }
                if (lane == 0) nxt[nnew] = ev;
                ++nnew;
                break;
            }
        }
        __syncwarp();
        int* t = cur; cur = nxt; nxt = t;
        nfree = nnew;
    }

    // ---- phase 3: shortest augmenting path for the remainder ----
    for (int fidx = 0; fidx < nfree; ++fidx) {
        int i = cur[fidx];
        unsigned usedmask = 0;
        #pragma unroll
        for (int s = 0; s < NSLOT; ++s) minv[s] = 3.0e38f;
        int cr = i, j0 = -1;

        while (true) {
            float ucr = u[cr];
            const float* crow = cost + cr * NQ;
            uint32_t bk = 0xffffffffu; int bi = 0x7fffffff;
            #pragma unroll
            for (int s = 0; s < NSLOT; ++s) {
                int col = s * 32 + lane;
                bool ok = (s < 9 || valid9) && !((usedmask >> s) & 1u);
                if (ok) {
                    float curv = crow[col] - ucr - vv[s];
                    if (curv < minv[s]) { minv[s] = curv; way[col] = j0; }
                    uint32_t k = fkey(minv[s]);
                    if (k < bk) { bk = k; bi = col; }
                }
            }
            uint32_t mk = redux_min(bk);
            float delta = funkey(mk);
            int j1 = (int)redux_min((bk == mk) ? (uint32_t)bi : 0xffffffffu);

            #pragma unroll
            for (int s = 0; s < NSLOT; ++s) {
                int col = s * 32 + lane;
                if (s < 9 || valid9) {
                    if ((usedmask >> s) & 1u) {
                        u[p[col]] += delta;
                        vv[s] -= delta;
                    } else {
                        minv[s] -= delta;
                    }
                }
            }
            if (lane == 0) u[i] += delta;
            __syncwarp();

            if (lane == (j1 & 31)) usedmask |= 1u << (j1 >> 5);
            j0 = j1;
            cr = p[j1];
            if (cr == -1) break;
            __syncwarp();
        }

        __syncwarp();
        if (lane == 0) {
            int j = j0;
            while (j != -1) {
                int jp = way[j];
                p[j] = (jp != -1) ? p[jp] : i;
                j = jp;
            }
        }
        __syncwarp();
    }

    if (lane == 0 && out_size >= NB * NQ * NM + 2 * NB * NM) {
        float* pi = out + (size_t)NB * NQ * NM + (size_t)b * NM;
        float* gi = pi + (size_t)NB * NM;
        int r = 0;
        for (int j = 0; j < NQ; ++j)
            if (p[j] >= 0) { pi[r] = (float)j; gi[r] = (float)p[j]; ++r; }
    }
}

// ===================== launch =====================
extern "C" void kernel_launch(void* const* d_in, const int* in_sizes, int n_in,
                              void* d_out, int out_size) {
    const float* pred_logits = (const float*)d_in[0];
    const float* pred_boxes  = (const float*)d_in[1];
    const float* pred_masks  = (const float*)d_in[2];
    const int*   gt_labels   = (const int*)d_in[3];
    const float* gt_boxes    = (const float*)d_in[4];
    const float* gt_masks    = (const float*)d_in[5];
    float* out = (float*)d_out;

    k_convert_pred<<<NB * NQ, 256>>>(pred_masks);
    k_convert_gt<<<NB * NM, 256>>>(gt_masks);

    cudaFuncSetAttribute(k_mask_gemm, cudaFuncAttributeMaxDynamicSharedMemorySize, GEMM_SMEM);
    k_mask_gemm<<<dim3(3, NB, KSPLIT), 256, GEMM_SMEM>>>();

    k_finalize<<<dim3(NQ, NB), 128>>>(pred_logits, pred_boxes, gt_labels, gt_boxes, out);

    cudaFuncSetAttribute(k_hungarian, cudaFuncAttributeMaxDynamicSharedMemorySize, HUNG_SMEM);
    k_hungarian<<<NB, HUNG_THREADS, HUNG_SMEM>>>(out, out_size);
}

// round 7
// speedup vs baseline: 1.9295x; 1.0694x over previous
#include <cuda_runtime.h>
#include <cuda_bf16.h>
#include <cstdint>
#include <cstddef>

// ---------------- problem constants (fixed shapes) ----------------
#define NB 8
#define NQ 300
#define NM 100
#define NCLS 81
#define HW 16384
#define QPAD 384           // 3 tiles of 128 queries
#define MPAD 128           // gt padded to 128 for N dim
#define KSPLIT 4
#define KLEN (HW / KSPLIT) // 4096 bf16 per K-split
#define BK 64              // K tile (bf16 elems) = 128B row
#define KT (KLEN / BK)     // 64 iterations

// ---------------- static device scratch (no allocations allowed) ----------------
__device__ __nv_bfloat16 g_PM[(size_t)NB * QPAD * HW];   // sigmoid(pred_masks), bf16
__device__ __nv_bfloat16 g_GM[(size_t)NB * MPAD * HW];   // gt_masks, bf16
__device__ float g_NUM[(size_t)KSPLIT * NB * NQ * NM];   // partial dot products
__device__ float g_pm_sum[NB * NQ];
__device__ float g_gm_sum[NB * NM];

// ===================== kernel 1: fused converts (pred sigmoid + gt) =====================
__global__ void __launch_bounds__(256) k_convert(const float* __restrict__ pm,
                                                 const float* __restrict__ gm) {
    int blk = blockIdx.x;
    float sum = 0.f;
    if (blk < NB * NQ) {                      // ---- pred path ----
        int b = blk / NQ, q = blk - b * NQ;
        const float4* src = reinterpret_cast<const float4*>(pm + (size_t)blk * HW);
        __nv_bfloat162* dst =
            reinterpret_cast<__nv_bfloat162*>(g_PM + ((size_t)b * QPAD + q) * HW);
        for (int i = threadIdx.x; i < HW / 4; i += 256) {
            float4 v = src[i];
            float s0 = 1.f / (1.f + __expf(-v.x));
            float s1 = 1.f / (1.f + __expf(-v.y));
            float s2 = 1.f / (1.f + __expf(-v.z));
            float s3 = 1.f / (1.f + __expf(-v.w));
            sum += (s0 + s1) + (s2 + s3);
            dst[2 * i]     = __floats2bfloat162_rn(s0, s1);
            dst[2 * i + 1] = __floats2bfloat162_rn(s2, s3);
        }
    } else {                                  // ---- gt path ----
        int bm = blk - NB * NQ;
        int b = bm / NM, m = bm - b * NM;
        const float4* src = reinterpret_cast<const float4*>(gm + (size_t)bm * HW);
        __nv_bfloat162* dst =
            reinterpret_cast<__nv_bfloat162*>(g_GM + ((size_t)b * MPAD + m) * HW);
        for (int i = threadIdx.x; i < HW / 4; i += 256) {
            float4 v = src[i];
            sum += (v.x + v.y) + (v.z + v.w);
            dst[2 * i]     = __floats2bfloat162_rn(v.x, v.y);
            dst[2 * i + 1] = __floats2bfloat162_rn(v.z, v.w);
        }
    }
    for (int o = 16; o; o >>= 1) sum += __shfl_down_sync(0xffffffffu, sum, o);
    __shared__ float ws[8];
    if ((threadIdx.x & 31) == 0) ws[threadIdx.x >> 5] = sum;
    __syncthreads();
    if (threadIdx.x == 0) {
        float t = 0.f;
        #pragma unroll
        for (int w = 0; w < 8; ++w) t += ws[w];
        if (blk < NB * NQ) g_pm_sum[blk];
        if (blk < NB * NQ) g_pm_sum[blk] = t;
        else g_gm_sum[blk - NB * NQ] = t;
    }
}

// ===================== kernel 2: mma.sync bf16 GEMM (dice numerator) =====================
#define TILE_BYTES 16384          // 128 rows x 128B
#define GEMM_SMEM (4 * TILE_BYTES)

__device__ __forceinline__ uint32_t sw128(uint32_t off) {
    return off ^ ((off >> 3) & 0x70);
}

__device__ __forceinline__ void cp_tile(const __nv_bfloat16* __restrict__ src,
                                        uint32_t dstBase) {
    int t = threadIdx.x;
    #pragma unroll
    for (int s = 0; s < 4; ++s) {
        int i = t + s * 256;                  // 0..1023
        int row = i >> 3, c16 = i & 7;
        unsigned long long g =
            __cvta_generic_to_global(src + (size_t)row * HW + c16 * 8);
        uint32_t off = sw128((uint32_t)(row * 128 + c16 * 16));
        asm volatile("cp.async.cg.shared.global [%0], [%1], 16;"
                     :: "r"(dstBase + off), "l"(g));
    }
}

__global__ void __launch_bounds__(256) k_mask_gemm() {
    extern __shared__ char smem[];
    uint32_t sA = (uint32_t)__cvta_generic_to_shared(smem);
    uint32_t sB = sA + 2 * TILE_BYTES;

    int tid = threadIdx.x, lane = tid & 31, warp = tid >> 5;
    int wm = warp & 1, wn = warp >> 1;        // 2 x 4 warp grid
    int warpRow = wm * 64, warpCol = wn * 32;

    int tile = blockIdx.x, b = blockIdx.y, ks = blockIdx.z;
    int q0 = tile * 128;

    const __nv_bfloat16* Abase = g_PM + ((size_t)b * QPAD + q0) * HW + (size_t)ks * KLEN;
    const __nv_bfloat16* Bbase = g_GM + (size_t)b * MPAD * HW + (size_t)ks * KLEN;

    float acc[4][4][4];
    #pragma unroll
    for (int i = 0; i < 4; ++i)
        #pragma unroll
        for (int j = 0; j < 4; ++j)
            #pragma unroll
            for (int r = 0; r < 4; ++r) acc[i][j][r] = 0.f;

    cp_tile(Abase, sA);
    cp_tile(Bbase, sB);
    asm volatile("cp.async.commit_group;");
    asm volatile("cp.async.wait_group 0;");
    __syncthreads();

    int rA = warpRow + (lane & 15);
    int cAsel = lane >> 4;
    int rB = warpCol + (lane & 7);
    int cBsel = (lane >> 3) & 1;

    int st = 0;
    for (int kt = 0; kt < KT; ++kt) {
        if (kt + 1 < KT) {
            int nst = st ^ 1;
            cp_tile(Abase + (size_t)(kt + 1) * BK, sA + nst * TILE_BYTES);
            cp_tile(Bbase + (size_t)(kt + 1) * BK, sB + nst * TILE_BYTES);
            asm volatile("cp.async.commit_group;");
        }
        uint32_t a0 = sA + st * TILE_BYTES;
        uint32_t b0 = sB + st * TILE_BYTES;

        #pragma unroll
        for (int kk = 0; kk < 4; ++kk) {
            uint32_t af[4][4], bf[4][2];
            #pragma unroll
            for (int mt = 0; mt < 4; ++mt) {
                uint32_t addr = a0 + sw128((uint32_t)((rA + mt * 16) * 128
                                                      + (kk * 2 + cAsel) * 16));
                asm volatile("ldmatrix.sync.aligned.m8n8.x4.shared.b16 "
                             "{%0,%1,%2,%3}, [%4];"
                             : "=r"(af[mt][0]), "=r"(af[mt][1]),
                               "=r"(af[mt][2]), "=r"(af[mt][3]) : "r"(addr));
            }
            #pragma unroll
            for (int nt = 0; nt < 4; ++nt) {
                uint32_t addr = b0 + sw128((uint32_t)((rB + nt * 8) * 128
                                                      + (kk * 2 + cBsel) * 16));
                asm volatile("ldmatrix.sync.aligned.m8n8.x2.shared.b16 "
                             "{%0,%1}, [%2];"
                             : "=r"(bf[nt][0]), "=r"(bf[nt][1]) : "r"(addr));
            }
            #pragma unroll
            for (int mt = 0; mt < 4; ++mt)
                #pragma unroll
                for (int nt = 0; nt < 4; ++nt) {
                    asm volatile(
                        "mma.sync.aligned.m16n8k16.row.col.f32.bf16.bf16.f32 "
                        "{%0,%1,%2,%3}, {%4,%5,%6,%7}, {%8,%9}, {%0,%1,%2,%3};"
                        : "+f"(acc[mt][nt][0]), "+f"(acc[mt][nt][1]),
                          "+f"(acc[mt][nt][2]), "+f"(acc[mt][nt][3])
                        : "r"(af[mt][0]), "r"(af[mt][1]),
                          "r"(af[mt][2]), "r"(af[mt][3]),
                          "r"(bf[nt][0]), "r"(bf[nt][1]));
                }
        }
        if (kt + 1 < KT) {
            asm volatile("cp.async.wait_group 0;");
        }
        __syncthreads();
        st ^= 1;
    }

    float* dst = g_NUM + ((size_t)ks * NB + b) * NQ * NM;
    int rowInTile = lane >> 2;
    int colInTile = (lane & 3) * 2;
    #pragma unroll
    for (int mt = 0; mt < 4; ++mt) {
        #pragma unroll
        for (int nt = 0; nt < 4; ++nt) {
            int qb = q0 + warpRow + mt * 16 + rowInTile;
            int mb = warpCol + nt * 8 + colInTile;
            #pragma unroll
            for (int r = 0; r < 4; ++r) {
                int q = qb + ((r >> 1) ? 8 : 0);
                int m = mb + (r & 1);
                if (q < NQ && m < NM)
                    dst[(size_t)q * NM + m] = acc[mt][nt][r];
            }
        }
    }
}

// ===================== kernel 3: assemble full cost matrix =====================
__global__ void __launch_bounds__(128) k_finalize(const float* __restrict__ logits,
                                                  const float* __restrict__ pboxes,
                                                  const int* __restrict__ glabels,
                                                  const float* __restrict__ gboxes,
                                                  float* __restrict__ out) {
    int q = blockIdx.x, b = blockIdx.y;
    int tid = threadIdx.x;
    __shared__ float probs[NCLS];
    __shared__ float red[128];

    const float* lg = logits + ((size_t)b * NQ + q) * NCLS;
    float x = (tid < NCLS) ? lg[tid] : -3.0e38f;
    red[tid] = x; __syncthreads();
    #pragma unroll
    for (int s = 64; s > 0; s >>= 1) { if (tid < s) red[tid] = fmaxf(red[tid], red[tid + s]); __syncthreads(); }
    float mx = red[0]; __syncthreads();
    float e = (tid < NCLS) ? __expf(x - mx) : 0.f;
    red[tid] = e; __syncthreads();
    #pragma unroll
    for (int s = 64; s > 0; s >>= 1) { if (tid < s) red[tid] += red[tid + s]; __syncthreads(); }
    float inv = 1.f / red[0];
    if (tid < NCLS) probs[tid] = e * inv;
    __syncthreads();

    const float* pb = pboxes + ((size_t)b * NQ + q) * 4;
    float px1 = pb[0], py1 = pb[1], px2 = pb[2], py2 = pb[3];
    float pa = (px2 - px1) * (py2 - py1);
    float psum = g_pm_sum[b * NQ + q];
    const size_t NSTR = (size_t)NB * NQ * NM;

    for (int m = tid; m < NM; m += 128) {
        int lbl = glabels[b * NM + m];
        float cclass = -probs[lbl];
        const float* gb = gboxes + ((size_t)b * NM + m) * 4;
        float gx1 = gb[0], gy1 = gb[1], gx2 = gb[2], gy2 = gb[3];
        float l1 = fabsf(px1 - gx1) + fabsf(py1 - gy1) + fabsf(px2 - gx2) + fabsf(py2 - gy2);
        float iw = fmaxf(fminf(px2, gx2) - fmaxf(px1, gx1), 0.f);
        float ih = fmaxf(fminf(py2, gy2) - fmaxf(py1, gy1), 0.f);
        float inter = iw * ih;
        float ga = (gx2 - gx1) * (gy2 - gy1);
        float uni = pa + ga - inter;
        float iou = inter / (uni + 1e-6f);
        float ew = fmaxf(fmaxf(px2, gx2) - fminf(px1, gx1), 0.f);
        float eh = fmaxf(fmaxf(py2, gy2) - fminf(py1, gy1), 0.f);
        float am = ew * eh;
        float giou = iou - (am - uni) / (am + 1e-6f);
        size_t ni = ((size_t)b * NQ + q) * NM + m;
        float dot = g_NUM[ni] + g_NUM[NSTR + ni] + g_NUM[2 * NSTR + ni] + g_NUM[3 * NSTR + ni];
        float den = psum + g_gm_sum[b * NM + m];
        float cmask = 1.f - (2.f * dot) / (den + 1e-6f);
        out[ni] = cclass + 5.f * (l1 - giou) + 2.f * cmask;
    }
}

// ===================== kernel 4: JV solver, parallel phase 1 + warp ARR/Dijkstra ==========
#define HUNG_THREADS 512
#define HUNG_SMEM (NM * 4 + NM * NQ * 4 + NQ * 8 + NM * 8 + NM * 4)
#define NSLOT 10

__device__ __forceinline__ uint32_t fkey(float f) {
    uint32_t u = __float_as_uint(f);
    return (u & 0x80000000u) ? ~u : (u | 0x80000000u);
}
__device__ __forceinline__ float funkey(uint32_t k) {
    uint32_t u = (k & 0x80000000u) ? (k & 0x7fffffffu) : ~k;
    return __uint_as_float(u);
}
__device__ __forceinline__ uint32_t redux_min(uint32_t v) {
    uint32_t d;
    asm volatile("redux.sync.min.u32 %0, %1, 0xffffffff;" : "=r"(d) : "r"(v));
    return d;
}

__global__ void __launch_bounds__(HUNG_THREADS) k_hungarian(float* __restrict__ out, int out_size) {
    extern __shared__ char sm[];
    float* u    = reinterpret_cast<float*>(sm);               // [100]
    float* cost = u + NM;                                     // [100][300] transposed
    int* p      = reinterpret_cast<int*>(cost + NM * NQ);     // [300]
    int* way    = p + NQ;                                     // [300]
    int* flA    = way + NQ;                                   // [100]
    int* flB    = flA + NM;                                   // [100]
    int* rowarg = flB + NM;                                   // [100]

    int b = blockIdx.x;
    int tid = threadIdx.x;
    const int lane = tid & 31;
    const int warp = tid >> 5;
    const float* C = out + (size_t)b * NQ * NM;

    for (int idx = tid; idx < NM * NQ; idx += HUNG_THREADS) {
        int q = idx / NM, m = idx - q * NM;
        cost[m * NQ + q] = C[idx];
    }
    for (int j = tid; j < NQ; j += HUNG_THREADS) p[j] = -1;
    __syncthreads();

    // ---- phase 1 (parallel): per-row minima across 16 warps ----
    const bool valid9 = (lane < 12);          // col 288..299 only
    for (int i = warp; i < NM; i += 16) {
        const float* crow = cost + i * NQ;
        uint32_t bk = 0xffffffffu; int bi = 0x7fffffff;
        #pragma unroll
        for (int s = 0; s < NSLOT; ++s) {
            int col = s * 32 + lane;
            if (s < 9 || valid9) {
                uint32_t k = fkey(crow[col]);
                if (k < bk) { bk = k; bi = col; }
            }
        }
        uint32_t mk = redux_min(bk);
        int jstar = (int)redux_min((bk == mk) ? (uint32_t)bi : 0xffffffffu);
        if (lane == 0) { u[i] = funkey(mk); rowarg[i] = jstar; }
    }
    __syncthreads();
    if (tid >= 32) return;

    float vv[NSLOT], minv[NSLOT];
    #pragma unroll
    for (int s = 0; s < NSLOT; ++s) vv[s] = 0.0f;

    // ---- greedy seed (serial bookkeeping only) ----
    int nfree = 0;
    for (int i = 0; i < NM; ++i) {
        int jstar = rowarg[i];
        int pj = p[jstar];
        __syncwarp();
        if (lane == 0) { if (pj == -1) p[jstar] = i; }
        if (pj != -1) { if (lane == 0) flA[nfree] = i; ++nfree; }
        __syncwarp();
    }

    // ---- phase 2: augmenting row reduction (<=2 passes) ----
    int* cur = flA; int* nxt = flB;
    for (int pass = 0; pass < 2 && nfree > 0; ++pass) {
        int nnew = 0;
        for (int k = 0; k < nfree; ++k) {
            int i = cur[k];
            for (;;) {
                const float* crow = cost + i * NQ;
                uint32_t keys[NSLOT];
                uint32_t bk = 0xffffffffu; int bi = 0x7fffffff;
                #pragma unroll
                for (int s = 0; s < NSLOT; ++s) {
                    int col = s * 32 + lane;
                    uint32_t kk = 0xffffffffu;
                    if (s < 9 || valid9) kk = fkey(crow[col] - vv[s]);
                    keys[s] = kk;
                    if (kk < bk) { bk = kk; bi = col; }
                }
                uint32_t u1k = redux_min(bk);
                int j1 = (int)redux_min((bk == u1k) ? (uint32_t)bi : 0xffffffffu);
                // second min (exclude column j1)
                uint32_t bk2 = 0xffffffffu; int bi2 = 0x7fffffff;
                #pragma unroll
                for (int s = 0; s < NSLOT; ++s) {
                    int col = s * 32 + lane;
                    if (col != j1 && keys[s] < bk2) { bk2 = keys[s]; bi2 = col; }
                }
                uint32_t u2k = redux_min(bk2);
                int j2 = (int)redux_min((bk2 == u2k) ? (uint32_t)bi2 : 0xffffffffu);

                float u1 = funkey(u1k), u2 = funkey(u2k);
                bool strict = (u1 < u2);
                int jt = j1;
                if (!strict) {
                    int pj1 = p[j1], pj2 = p[j2];
                    if (pj1 != -1 && pj2 == -1) jt = j2;
                }
                __syncwarp();
                int ev = p[jt];               // broadcast read
                __syncwarp();
                if (lane == 0) { u[i] = u2; p[jt] = i; }
                if (strict && lane == (jt & 31)) vv[jt >> 5] -= (u2 - u1);
                __syncwarp();

                if (ev == -1) break;
                if (strict) { i = ev; continue; }
                if (lane == 0) nxt[nnew] = ev;
                ++nnew;
                break;
            }
        }
        __syncwarp();
        int* t = cur; cur = nxt; nxt = t;
        nfree = nnew;
    }

    // ---- phase 3: shortest augmenting path for the remainder ----
    for (int fidx = 0; fidx < nfree; ++fidx) {
        int i = cur[fidx];
        unsigned usedmask = 0;
        #pragma unroll
        for (int s = 0; s < NSLOT; ++s) minv[s] = 3.0e38f;
        int cr = i, j0 = -1;

        while (true) {
            float ucr = u[cr];
            const float* crow = cost + cr * NQ;
            uint32_t bk = 0xffffffffu; int bi = 0x7fffffff;
            #pragma unroll
            for (int s = 0; s < NSLOT; ++s) {
                int col = s * 32 + lane;
                bool ok = (s < 9 || valid9) && !((usedmask >> s) & 1u);
                if (ok) {
                    float curv = crow[col] - ucr - vv[s];
                    if (curv < minv[s]) { minv[s] = curv; way[col] = j0; }
                    uint32_t k = fkey(minv[s]);
                    if (k < bk) { bk = k; bi = col; }
                }
            }
            uint32_t mk = redux_min(bk);
            float delta = funkey(mk);
            int j1 = (int)redux_min((bk == mk) ? (uint32_t)bi : 0xffffffffu);

            #pragma unroll
            for (int s = 0; s < NSLOT; ++s) {
                int col = s * 32 + lane;
                if (s < 9 || valid9) {
                    if ((usedmask >> s) & 1u) {
                        u[p[col]] += delta;
                        vv[s] -= delta;
                    } else {
                        minv[s] -= delta;
                    }
                }
            }
            if (lane == 0) u[i] += delta;
            __syncwarp();

            if (lane == (j1 & 31)) usedmask |= 1u << (j1 >> 5);
            j0 = j1;
            cr = p[j1];
            if (cr == -1) break;
            __syncwarp();
        }

        __syncwarp();
        if (lane == 0) {
            int j = j0;
            while (j != -1) {
                int jp = way[j];
                p[j] = (jp != -1) ? p[jp] : i;
                j = jp;
            }
        }
        __syncwarp();
    }

    if (lane == 0 && out_size >= NB * NQ * NM + 2 * NB * NM) {
        float* pi = out + (size_t)NB * NQ * NM + (size_t)b * NM;
        float* gi = pi + (size_t)NB * NM;
        int r = 0;
        for (int j = 0; j < NQ; ++j)
            if (p[j] >= 0) { pi[r] = (float)j; gi[r] = (float)p[j]; ++r; }
    }
}

// ===================== launch =====================
extern "C" void kernel_launch(void* const* d_in, const int* in_sizes, int n_in,
                              void* d_out, int out_size) {
    const float* pred_logits = (const float*)d_in[0];
    const float* pred_boxes  = (const float*)d_in[1];
    const float* pred_masks  = (const float*)d_in[2];
    const int*   gt_labels   = (const int*)d_in[3];
    const float* gt_boxes    = (const float*)d_in[4];
    const float* gt_masks    = (const float*)d_in[5];
    float* out = (float*)d_out;

    k_convert<<<NB * NQ + NB * NM, 256>>>(pred_masks, gt_masks);

    cudaFuncSetAttribute(k_mask_gemm, cudaFuncAttributeMaxDynamicSharedMemorySize, GEMM_SMEM);
    k_mask_gemm<<<dim3(3, NB, KSPLIT), 256, GEMM_SMEM>>>();

    k_finalize<<<dim3(NQ, NB), 128>>>(pred_logits, pred_boxes, gt_labels, gt_boxes, out);

    cudaFuncSetAttribute(k_hungarian, cudaFuncAttributeMaxDynamicSharedMemorySize, HUNG_SMEM);
    k_hungarian<<<NB, HUNG_THREADS, HUNG_SMEM>>>(out, out_size);
}

// round 8
// speedup vs baseline: 2.0649x; 1.0702x over previous
#include <cuda_runtime.h>
#include <cuda_bf16.h>
#include <cstdint>
#include <cstddef>

// ---------------- problem constants (fixed shapes) ----------------
#define NB 8
#define NQ 300
#define NM 100
#define NCLS 81
#define HW 16384
#define QPAD 384           // 3 tiles of 128 queries
#define MPAD 128           // gt padded to 128 for N dim
#define KSPLIT 4
#define KLEN (HW / KSPLIT) // 4096 bf16 per K-split
#define BK 64              // K tile (bf16 elems) = 128B row
#define KT (KLEN / BK)     // 64 iterations

// ---------------- static device scratch (no allocations allowed) ----------------
__device__ __nv_bfloat16 g_PM[(size_t)NB * QPAD * HW];   // sigmoid(pred_masks), bf16
__device__ __nv_bfloat16 g_GM[(size_t)NB * MPAD * HW];   // gt_masks, bf16
__device__ float g_NUM[(size_t)KSPLIT * NB * NQ * NM];   // partial dot products
__device__ float g_pm_sum[NB * NQ];
__device__ float g_gm_sum[NB * NM];

// ===================== kernel 1: fused converts (pred sigmoid + gt) =====================
__global__ void __launch_bounds__(256) k_convert(const float* __restrict__ pm,
                                                 const float* __restrict__ gm) {
    int blk = blockIdx.x;
    float sum = 0.f;
    if (blk < NB * NQ) {                      // ---- pred path ----
        int b = blk / NQ, q = blk - b * NQ;
        const float4* src = reinterpret_cast<const float4*>(pm + (size_t)blk * HW);
        uint2* dst = reinterpret_cast<uint2*>(g_PM + ((size_t)b * QPAD + q) * HW);
        for (int i = threadIdx.x; i < HW / 4; i += 256) {
            float4 v = src[i];
            float s0 = 1.f / (1.f + __expf(-v.x));
            float s1 = 1.f / (1.f + __expf(-v.y));
            float s2 = 1.f / (1.f + __expf(-v.z));
            float s3 = 1.f / (1.f + __expf(-v.w));
            sum += (s0 + s1) + (s2 + s3);
            __nv_bfloat162 lo = __floats2bfloat162_rn(s0, s1);
            __nv_bfloat162 hi = __floats2bfloat162_rn(s2, s3);
            dst[i] = make_uint2(*reinterpret_cast<uint32_t*>(&lo),
                                *reinterpret_cast<uint32_t*>(&hi));
        }
    } else {                                  // ---- gt path ----
        int bm = blk - NB * NQ;
        int b = bm / NM, m = bm - b * NM;
        const float4* src = reinterpret_cast<const float4*>(gm + (size_t)bm * HW);
        uint2* dst = reinterpret_cast<uint2*>(g_GM + ((size_t)b * MPAD + m) * HW);
        for (int i = threadIdx.x; i < HW / 4; i += 256) {
            float4 v = src[i];
            sum += (v.x + v.y) + (v.z + v.w);
            __nv_bfloat162 lo = __floats2bfloat162_rn(v.x, v.y);
            __nv_bfloat162 hi = __floats2bfloat162_rn(v.z, v.w);
            dst[i] = make_uint2(*reinterpret_cast<uint32_t*>(&lo),
                                *reinterpret_cast<uint32_t*>(&hi));
        }
    }
    for (int o = 16; o; o >>= 1) sum += __shfl_down_sync(0xffffffffu, sum, o);
    __shared__ float ws[8];
    if ((threadIdx.x & 31) == 0) ws[threadIdx.x >> 5] = sum;
    __syncthreads();
    if (threadIdx.x == 0) {
        float t = 0.f;
        #pragma unroll
        for (int w = 0; w < 8; ++w) t += ws[w];
        if (blk < NB * NQ) g_pm_sum[blk] = t;
        else g_gm_sum[blk - NB * NQ] = t;
    }
}

// ===================== kernel 2: mma.sync bf16 GEMM, 3-stage cp.async =====================
#define TILE_BYTES 16384          // 128 rows x 128B
#define GEMM_SMEM (6 * TILE_BYTES)

__device__ __forceinline__ uint32_t sw128(uint32_t off) {
    return off ^ ((off >> 3) & 0x70);
}

__device__ __forceinline__ void cp_tile(const __nv_bfloat16* __restrict__ src,
                                        uint32_t dstBase) {
    int t = threadIdx.x;
    #pragma unroll
    for (int s = 0; s < 4; ++s) {
        int i = t + s * 256;                  // 0..1023
        int row = i >> 3, c16 = i & 7;
        unsigned long long g =
            __cvta_generic_to_global(src + (size_t)row * HW + c16 * 8);
        uint32_t off = sw128((uint32_t)(row * 128 + c16 * 16));
        asm volatile("cp.async.cg.shared.global [%0], [%1], 16;"
                     :: "r"(dstBase + off), "l"(g));
    }
}

__global__ void __launch_bounds__(256) k_mask_gemm() {
    extern __shared__ char smem[];
    uint32_t sA = (uint32_t)__cvta_generic_to_shared(smem);
    uint32_t sB = sA + 3 * TILE_BYTES;

    int tid = threadIdx.x, lane = tid & 31, warp = tid >> 5;
    int wm = warp & 1, wn = warp >> 1;        // 2 x 4 warp grid
    int warpRow = wm * 64, warpCol = wn * 32;

    int tile = blockIdx.x, b = blockIdx.y, ks = blockIdx.z;
    int q0 = tile * 128;

    const __nv_bfloat16* Abase = g_PM + ((size_t)b * QPAD + q0) * HW + (size_t)ks * KLEN;
    const __nv_bfloat16* Bbase = g_GM + (size_t)b * MPAD * HW + (size_t)ks * KLEN;

    float acc[4][4][4];
    #pragma unroll
    for (int i = 0; i < 4; ++i)
        #pragma unroll
        for (int j = 0; j < 4; ++j)
            #pragma unroll
            for (int r = 0; r < 4; ++r) acc[i][j][r] = 0.f;

    // prologue: stages 0 and 1 in flight
    cp_tile(Abase, sA);
    cp_tile(Bbase, sB);
    asm volatile("cp.async.commit_group;");
    cp_tile(Abase + BK, sA + TILE_BYTES);
    cp_tile(Bbase + BK, sB + TILE_BYTES);
    asm volatile("cp.async.commit_group;");
    asm volatile("cp.async.wait_group 1;");   // stage 0 complete
    __syncthreads();

    int rA = warpRow + (lane & 15);
    int cAsel = lane >> 4;
    int rB = warpCol + (lane & 7);
    int cBsel = (lane >> 3) & 1;

    int st = 0, pst = 2;
    for (int kt = 0; kt < KT; ++kt) {
        int pf = kt + 2;
        if (pf < KT) {
            cp_tile(Abase + (size_t)pf * BK, sA + pst * TILE_BYTES);
            cp_tile(Bbase + (size_t)pf * BK, sB + pst * TILE_BYTES);
            asm volatile("cp.async.commit_group;");
        }
        uint32_t a0 = sA + st * TILE_BYTES;
        uint32_t b0 = sB + st * TILE_BYTES;

        #pragma unroll
        for (int kk = 0; kk < 4; ++kk) {
            uint32_t af[4][4], bf[4][2];
            #pragma unroll
            for (int mt = 0; mt < 4; ++mt) {
                uint32_t addr = a0 + sw128((uint32_t)((rA + mt * 16) * 128
                                                      + (kk * 2 + cAsel) * 16));
                asm volatile("ldmatrix.sync.aligned.m8n8.x4.shared.b16 "
                             "{%0,%1,%2,%3}, [%4];"
                             : "=r"(af[mt][0]), "=r"(af[mt][1]),
                               "=r"(af[mt][2]), "=r"(af[mt][3]) : "r"(addr));
            }
            #pragma unroll
            for (int nt = 0; nt < 4; ++nt) {
                uint32_t addr = b0 + sw128((uint32_t)((rB + nt * 8) * 128
                                                      + (kk * 2 + cBsel) * 16));
                asm volatile("ldmatrix.sync.aligned.m8n8.x2.shared.b16 "
                             "{%0,%1}, [%2];"
                             : "=r"(bf[nt][0]), "=r"(bf[nt][1]) : "r"(addr));
            }
            #pragma unroll
            for (int mt = 0; mt < 4; ++mt)
                #pragma unroll
                for (int nt = 0; nt < 4; ++nt) {
                    asm volatile(
                        "mma.sync.aligned.m16n8k16.row.col.f32.bf16.bf16.f32 "
                        "{%0,%1,%2,%3}, {%4,%5,%6,%7}, {%8,%9}, {%0,%1,%2,%3};"
                        : "+f"(acc[mt][nt][0]), "+f"(acc[mt][nt][1]),
                          "+f"(acc[mt][nt][2]), "+f"(acc[mt][nt][3])
                        : "r"(af[mt][0]), "r"(af[mt][1]),
                          "r"(af[mt][2]), "r"(af[mt][3]),
                          "r"(bf[nt][0]), "r"(bf[nt][1]));
                }
        }
        if (kt + 1 < KT) {
            if (pf < KT) { asm volatile("cp.async.wait_group 1;"); }
            else         { asm volatile("cp.async.wait_group 0;"); }
        }
        __syncthreads();
        st = (st == 2) ? 0 : st + 1;
        pst = (pst == 2) ? 0 : pst + 1;
    }

    float* dst = g_NUM + ((size_t)ks * NB + b) * NQ * NM;
    int rowInTile = lane >> 2;
    int colInTile = (lane & 3) * 2;
    #pragma unroll
    for (int mt = 0; mt < 4; ++mt) {
        #pragma unroll
        for (int nt = 0; nt < 4; ++nt) {
            int qb = q0 + warpRow + mt * 16 + rowInTile;
            int mb = warpCol + nt * 8 + colInTile;
            #pragma unroll
            for (int r = 0; r < 4; ++r) {
                int q = qb + ((r >> 1) ? 8 : 0);
                int m = mb + (r & 1);
                if (q < NQ && m < NM)
                    dst[(size_t)q * NM + m] = acc[mt][nt][r];
            }
        }
    }
}

// ===================== kernel 3: assemble full cost matrix =====================
__global__ void __launch_bounds__(128) k_finalize(const float* __restrict__ logits,
                                                  const float* __restrict__ pboxes,
                                                  const int* __restrict__ glabels,
                                                  const float* __restrict__ gboxes,
                                                  float* __restrict__ out) {
    int q = blockIdx.x, b = blockIdx.y;
    int tid = threadIdx.x;
    __shared__ float probs[NCLS];
    __shared__ float red[128];

    const float* lg = logits + ((size_t)b * NQ + q) * NCLS;
    float x = (tid < NCLS) ? lg[tid] : -3.0e38f;
    red[tid] = x; __syncthreads();
    #pragma unroll
    for (int s = 64; s > 0; s >>= 1) { if (tid < s) red[tid] = fmaxf(red[tid], red[tid + s]); __syncthreads(); }
    float mx = red[0]; __syncthreads();
    float e = (tid < NCLS) ? __expf(x - mx) : 0.f;
    red[tid] = e; __syncthreads();
    #pragma unroll
    for (int s = 64; s > 0; s >>= 1) { if (tid < s) red[tid] += red[tid + s]; __syncthreads(); }
    float inv = 1.f / red[0];
    if (tid < NCLS) probs[tid] = e * inv;
    __syncthreads();

    const float* pb = pboxes + ((size_t)b * NQ + q) * 4;
    float px1 = pb[0], py1 = pb[1], px2 = pb[2], py2 = pb[3];
    float pa = (px2 - px1) * (py2 - py1);
    float psum = g_pm_sum[b * NQ + q];
    const size_t NSTR = (size_t)NB * NQ * NM;

    for (int m = tid; m < NM; m += 128) {
        int lbl = glabels[b * NM + m];
        float cclass = -probs[lbl];
        const float* gb = gboxes + ((size_t)b * NM + m) * 4;
        float gx1 = gb[0], gy1 = gb[1], gx2 = gb[2], gy2 = gb[3];
        float l1 = fabsf(px1 - gx1) + fabsf(py1 - gy1) + fabsf(px2 - gx2) + fabsf(py2 - gy2);
        float iw = fmaxf(fminf(px2, gx2) - fmaxf(px1, gx1), 0.f);
        float ih = fmaxf(fminf(py2, gy2) - fmaxf(py1, gy1), 0.f);
        float inter = iw * ih;
        float ga = (gx2 - gx1) * (gy2 - gy1);
        float uni = pa + ga - inter;
        float iou = inter / (uni + 1e-6f);
        float ew = fmaxf(fmaxf(px2, gx2) - fminf(px1, gx1), 0.f);
        float eh = fmaxf(fmaxf(py2, gy2) - fminf(py1, gy1), 0.f);
        float am = ew * eh;
        float giou = iou - (am - uni) / (am + 1e-6f);
        size_t ni = ((size_t)b * NQ + q) * NM + m;
        float dot = g_NUM[ni] + g_NUM[NSTR + ni] + g_NUM[2 * NSTR + ni] + g_NUM[3 * NSTR + ni];
        float den = psum + g_gm_sum[b * NM + m];
        float cmask = 1.f - (2.f * dot) / (den + 1e-6f);
        out[ni] = cclass + 5.f * (l1 - giou) + 2.f * cmask;
    }
}

// ===================== kernel 4: JV solver (low-sync warp inner loops) =====================
#define HUNG_THREADS 512
#define NQP 301                   // padded cost stride (conflict-free transpose stores)
#define HUNG_SMEM (NM * 4 + NM * NQP * 4 + NQ * 8 + NM * 8 + NM * 4)
#define NSLOT 10

__device__ __forceinline__ uint32_t fkey(float f) {
    uint32_t u = __float_as_uint(f);
    return (u & 0x80000000u) ? ~u : (u | 0x80000000u);
}
__device__ __forceinline__ float funkey(uint32_t k) {
    uint32_t u = (k & 0x80000000u) ? (k & 0x7fffffffu) : ~k;
    return __uint_as_float(u);
}
__device__ __forceinline__ uint32_t redux_min(uint32_t v) {
    uint32_t d;
    asm volatile("redux.sync.min.u32 %0, %1, 0xffffffff;" : "=r"(d) : "r"(v));
    return d;
}

__global__ void __launch_bounds__(HUNG_THREADS) k_hungarian(float* __restrict__ out, int out_size) {
    extern __shared__ char sm[];
    float* u    = reinterpret_cast<float*>(sm);               // [100]
    float* cost = u + NM;                                     // [100][301] transposed
    int* p      = reinterpret_cast<int*>(cost + NM * NQP);    // [300]
    int* way    = p + NQ;                                     // [300]
    int* flA    = way + NQ;                                   // [100]
    int* flB    = flA + NM;                                   // [100]
    int* rowarg = flB + NM;                                   // [100]

    int b = blockIdx.x;
    int tid = threadIdx.x;
    const int lane = tid & 31;
    const int warp = tid >> 5;
    const float* C = out + (size_t)b * NQ * NM;

    for (int idx = tid; idx < NM * NQ; idx += HUNG_THREADS) {
        int q = idx / NM, m = idx - q * NM;
        cost[m * NQP + q] = C[idx];
    }
    for (int j = tid; j < NQ; j += HUNG_THREADS) p[j] = -1;
    __syncthreads();

    // ---- phase 1 (parallel): per-row minima across 16 warps ----
    const bool valid9 = (lane < 12);          // col 288..299 only
    for (int i = warp; i < NM; i += 16) {
        const float* crow = cost + i * NQP;
        float bv = 3.0e38f; int bi = 0x7fffffff;
        #pragma unroll
        for (int s = 0; s < NSLOT; ++s) {
            int col = s * 32 + lane;
            if (s < 9 || valid9) {
                float v = crow[col];
                if (v < bv) { bv = v; bi = col; }
            }
        }
        uint32_t k = fkey(bv);
        uint32_t mk = redux_min(k);
        int jstar = (int)redux_min((k == mk) ? (uint32_t)bi : 0xffffffffu);
        if (lane == 0) { u[i] = funkey(mk); rowarg[i] = jstar; }
    }
    __syncthreads();
    if (tid >= 32) return;

    float vv[NSLOT], minv[NSLOT];
    #pragma unroll
    for (int s = 0; s < NSLOT; ++s) vv[s] = 0.0f;

    // ---- greedy seed (lane-0 scalar bookkeeping) ----
    int nfree = 0;
    if (lane == 0) {
        for (int i = 0; i < NM; ++i) {
            int js = rowarg[i];
            if (p[js] == -1) p[js] = i;
            else flA[nfree++] = i;
        }
    }
    __syncwarp();
    nfree = __shfl_sync(0xffffffffu, nfree, 0);

    // ---- phase 2: augmenting row reduction (<=4 passes) ----
    int* cur = flA; int* nxt = flB;
    for (int pass = 0; pass < 4 && nfree > 0; ++pass) {
        int nnew = 0;
        for (int k = 0; k < nfree; ++k) {
            int i = cur[k];
            for (;;) {
                const float* crow = cost + i * NQP;
                float fv[NSLOT];
                float b1 = 3.0e38f; int c1 = 0x7fffffff;
                #pragma unroll
                for (int s = 0; s < NSLOT; ++s) {
                    int col = s * 32 + lane;
                    float val = 3.0e38f;
                    if (s < 9 || valid9) val = crow[col] - vv[s];
                    fv[s] = val;
                    if (val < b1) { b1 = val; c1 = col; }
                }
                uint32_t k1 = fkey(b1);
                uint32_t u1k = redux_min(k1);
                int j1 = (int)redux_min((k1 == u1k) ? (uint32_t)c1 : 0xffffffffu);
                // second min (exclude column j1)
                float b2 = 3.0e38f; int c2 = 0x7fffffff;
                #pragma unroll
                for (int s = 0; s < NSLOT; ++s) {
                    int col = s * 32 + lane;
                    if (col != j1 && fv[s] < b2) { b2 = fv[s]; c2 = col; }
                }
                uint32_t k2 = fkey(b2);
                uint32_t u2k = redux_min(k2);
                float u1 = funkey(u1k), u2 = funkey(u2k);
                bool strict = (u1 < u2);
                int j2 = 0;
                if (!strict)
                    j2 = (int)redux_min((k2 == u2k) ? (uint32_t)c2 : 0xffffffffu);

                int pack = 0;
                if (lane == 0) {
                    int jt = j1;
                    if (!strict) {
                        int pj1 = p[j1], pj2 = p[j2];
                        if (pj1 != -1 && pj2 == -1) jt = j2;
                    }
                    int ev = p[jt];
                    u[i] = u2; p[jt] = i;
                    pack = (jt << 9) | (ev + 1);
                }
                pack = __shfl_sync(0xffffffffu, pack, 0);
                int jt = pack >> 9;
                int ev = (pack & 511) - 1;
                if (strict && lane == (jt & 31)) vv[jt >> 5] -= (u2 - u1);

                if (ev == -1) break;
                if (strict) { i = ev; continue; }
                if (lane == 0) nxt[nnew] = ev;
                ++nnew;
                break;
            }
        }
        __syncwarp();
        int* t = cur; cur = nxt; nxt = t;
        nfree = nnew;
    }

    // ---- phase 3: shortest augmenting path for the remainder ----
    for (int fidx = 0; fidx < nfree; ++fidx) {
        int i = cur[fidx];
        unsigned usedmask = 0;
        #pragma unroll
        for (int s = 0; s < NSLOT; ++s) minv[s] = 3.0e38f;
        int cr = i, j0 = -1;

        while (true) {
            float ucr = u[cr];
            const float* crow = cost + cr * NQP;
            float bv = 3.0e38f; int bi = 0x7fffffff;
            #pragma unroll
            for (int s = 0; s < NSLOT; ++s) {
                int col = s * 32 + lane;
                bool ok = (s < 9 || valid9) && !((usedmask >> s) & 1u);
                if (ok) {
                    float cv = crow[col] - ucr - vv[s];
                    if (cv < minv[s]) { minv[s] = cv; way[col] = j0; }
                    if (minv[s] < bv) { bv = minv[s]; bi = col; }
                }
            }
            uint32_t k = fkey(bv);
            uint32_t mk = redux_min(k);
            float delta = funkey(mk);
            int j1 = (int)redux_min((k == mk) ? (uint32_t)bi : 0xffffffffu);

            #pragma unroll
            for (int s = 0; s < NSLOT; ++s) {
                int col = s * 32 + lane;
                if (s < 9 || valid9) {
                    if ((usedmask >> s) & 1u) {
                        u[p[col]] += delta;
                        vv[s] -= delta;
                    } else {
                        minv[s] -= delta;
                    }
                }
            }
            if (lane == 0) u[i] += delta;
            if (lane == (j1 & 31)) usedmask |= 1u << (j1 >> 5);
            j0 = j1;
            cr = p[j1];
            __syncwarp();
            if (cr == -1) break;
        }

        if (lane == 0) {
            int j = j0;
            while (j != -1) {
                int jp = way[j];
                p[j] = (jp != -1) ? p[jp] : i;
                j = jp;
            }
        }
        __syncwarp();
    }

    if (lane == 0 && out_size >= NB * NQ * NM + 2 * NB * NM) {
        float* pi = out + (size_t)NB * NQ * NM + (size_t)b * NM;
        float* gi = pi + (size_t)NB * NM;
        int r = 0;
        for (int j = 0; j < NQ; ++j)
            if (p[j] >= 0) { pi[r] = (float)j; gi[r] = (float)p[j]; ++r; }
    }
}

// ===================== launch =====================
extern "C" void kernel_launch(void* const* d_in, const int* in_sizes, int n_in,
                              void* d_out, int out_size) {
    const float* pred_logits = (const float*)d_in[0];
    const float* pred_boxes  = (const float*)d_in[1];
    const float* pred_masks  = (const float*)d_in[2];
    const int*   gt_labels   = (const int*)d_in[3];
    const float* gt_boxes    = (const float*)d_in[4];
    const float* gt_masks    = (const float*)d_in[5];
    float* out = (float*)d_out;

    k_convert<<<NB * NQ + NB * NM, 256>>>(pred_masks, gt_masks);

    cudaFuncSetAttribute(k_mask_gemm, cudaFuncAttributeMaxDynamicSharedMemorySize, GEMM_SMEM);
    k_mask_gemm<<<dim3(3, NB, KSPLIT), 256, GEMM_SMEM>>>();

    k_finalize<<<dim3(NQ, NB), 128>>>(pred_logits, pred_boxes, gt_labels, gt_boxes, out);

    cudaFuncSetAttribute(k_hungarian, cudaFuncAttributeMaxDynamicSharedMemorySize, HUNG_SMEM);
    k_hungarian<<<NB, HUNG_THREADS, HUNG_SMEM>>>(out, out_size);
}

// round 9
// speedup vs baseline: 2.1951x; 1.0630x over previous
#include <cuda_runtime.h>
#include <cuda_bf16.h>
#include <cstdint>
#include <cstddef>

// ---------------- problem constants (fixed shapes) ----------------
#define NB 8
#define NQ 300
#define NM 100
#define NCLS 81
#define HW 16384
#define QPAD 384           // 4 tiles of 96 queries
#define MPAD 128           // gt padded to 128 for N dim
#define KSPLIT 4
#define KLEN (HW / KSPLIT) // 4096 bf16 per K-split
#define BK 64              // K tile (bf16 elems) = 128B row
#define KT (KLEN / BK)     // 64 iterations
#define MT 96              // M tile rows (queries per CTA)
#define NQT 4              // number of Q tiles

// ---------------- static device scratch (no allocations allowed) ----------------
__device__ __nv_bfloat16 g_PM[(size_t)NB * QPAD * HW];   // sigmoid(pred_masks), bf16
__device__ __nv_bfloat16 g_GM[(size_t)NB * MPAD * HW];   // gt_masks, bf16
__device__ float g_NUM[(size_t)KSPLIT * NB * NQ * NM];   // partial dot products
__device__ float g_pm_sum[NB * NQ];
__device__ float g_gm_sum[NB * NM];

// ===================== kernel 1: fused converts (pred sigmoid + gt) =====================
__global__ void __launch_bounds__(256) k_convert(const float* __restrict__ pm,
                                                 const float* __restrict__ gm) {
    int blk = blockIdx.x;
    float sum = 0.f;
    if (blk < NB * NQ) {                      // ---- pred path ----
        int b = blk / NQ, q = blk - b * NQ;
        const float4* src = reinterpret_cast<const float4*>(pm + (size_t)blk * HW);
        uint2* dst = reinterpret_cast<uint2*>(g_PM + ((size_t)b * QPAD + q) * HW);
        for (int i = threadIdx.x; i < HW / 4; i += 256) {
            float4 v = src[i];
            float s0 = 1.f / (1.f + __expf(-v.x));
            float s1 = 1.f / (1.f + __expf(-v.y));
            float s2 = 1.f / (1.f + __expf(-v.z));
            float s3 = 1.f / (1.f + __expf(-v.w));
            sum += (s0 + s1) + (s2 + s3);
            __nv_bfloat162 lo = __floats2bfloat162_rn(s0, s1);
            __nv_bfloat162 hi = __floats2bfloat162_rn(s2, s3);
            dst[i] = make_uint2(*reinterpret_cast<uint32_t*>(&lo),
                                *reinterpret_cast<uint32_t*>(&hi));
        }
    } else {                                  // ---- gt path ----
        int bm = blk - NB * NQ;
        int b = bm / NM, m = bm - b * NM;
        const float4* src = reinterpret_cast<const float4*>(gm + (size_t)bm * HW);
        uint2* dst = reinterpret_cast<uint2*>(g_GM + ((size_t)b * MPAD + m) * HW);
        for (int i = threadIdx.x; i < HW / 4; i += 256) {
            float4 v = src[i];
            sum += (v.x + v.y) + (v.z + v.w);
            __nv_bfloat162 lo = __floats2bfloat162_rn(v.x, v.y);
            __nv_bfloat162 hi = __floats2bfloat162_rn(v.z, v.w);
            dst[i] = make_uint2(*reinterpret_cast<uint32_t*>(&lo),
                                *reinterpret_cast<uint32_t*>(&hi));
        }
    }
    for (int o = 16; o; o >>= 1) sum += __shfl_down_sync(0xffffffffu, sum, o);
    __shared__ float ws[8];
    if ((threadIdx.x & 31) == 0) ws[threadIdx.x >> 5] = sum;
    __syncthreads();
    if (threadIdx.x == 0) {
        float t = 0.f;
        #pragma unroll
        for (int w = 0; w < 8; ++w) t += ws[w];
        if (blk < NB * NQ) g_pm_sum[blk] = t;
        else g_gm_sum[blk - NB * NQ] = t;
    }
}

// ===================== kernel 2: mma.sync bf16 GEMM, 96-row tiles, 3-stage =====================
#define A_TILE (MT * 128)         // 12288 bytes
#define B_TILE (128 * 128)        // 16384 bytes
#define GEMM_SMEM (3 * (A_TILE + B_TILE))   // 86016

__device__ __forceinline__ uint32_t sw128(uint32_t off) {
    return off ^ ((off >> 3) & 0x70);
}

__device__ __forceinline__ void cp_tileA(const __nv_bfloat16* __restrict__ src,
                                         uint32_t dstBase) {
    int t = threadIdx.x;
    #pragma unroll
    for (int s = 0; s < 3; ++s) {
        int i = t + s * 256;                  // 0..767 (96 rows x 8 chunks)
        int row = i >> 3, c16 = i & 7;
        unsigned long long g =
            __cvta_generic_to_global(src + (size_t)row * HW + c16 * 8);
        uint32_t off = sw128((uint32_t)(row * 128 + c16 * 16));
        asm volatile("cp.async.cg.shared.global [%0], [%1], 16;"
                     :: "r"(dstBase + off), "l"(g));
    }
}

__device__ __forceinline__ void cp_tileB(const __nv_bfloat16* __restrict__ src,
                                         uint32_t dstBase) {
    int t = threadIdx.x;
    #pragma unroll
    for (int s = 0; s < 4; ++s) {
        int i = t + s * 256;                  // 0..1023 (128 rows x 8 chunks)
        int row = i >> 3, c16 = i & 7;
        unsigned long long g =
            __cvta_generic_to_global(src + (size_t)row * HW + c16 * 8);
        uint32_t off = sw128((uint32_t)(row * 128 + c16 * 16));
        asm volatile("cp.async.cg.shared.global [%0], [%1], 16;"
                     :: "r"(dstBase + off), "l"(g));
    }
}

__global__ void __launch_bounds__(256) k_mask_gemm() {
    extern __shared__ char smem[];
    uint32_t sA = (uint32_t)__cvta_generic_to_shared(smem);
    uint32_t sB = sA + 3 * A_TILE;

    int tid = threadIdx.x, lane = tid & 31, warp = tid >> 5;
    int wm = warp & 1, wn = warp >> 1;        // 2 x 4 warp grid
    int warpRow = wm * 48, warpCol = wn * 32; // 2x48 = 96 rows, 4x32 = 128 cols

    int tile = blockIdx.x, b = blockIdx.y, ks = blockIdx.z;
    int q0 = tile * MT;

    const __nv_bfloat16* Abase = g_PM + ((size_t)b * QPAD + q0) * HW + (size_t)ks * KLEN;
    const __nv_bfloat16* Bbase = g_GM + (size_t)b * MPAD * HW + (size_t)ks * KLEN;

    float acc[3][4][4];
    #pragma unroll
    for (int i = 0; i < 3; ++i)
        #pragma unroll
        for (int j = 0; j < 4; ++j)
            #pragma unroll
            for (int r = 0; r < 4; ++r) acc[i][j][r] = 0.f;

    // prologue: stages 0 and 1 in flight
    cp_tileA(Abase, sA);
    cp_tileB(Bbase, sB);
    asm volatile("cp.async.commit_group;");
    cp_tileA(Abase + BK, sA + A_TILE);
    cp_tileB(Bbase + BK, sB + B_TILE);
    asm volatile("cp.async.commit_group;");
    asm volatile("cp.async.wait_group 1;");   // stage 0 complete
    __syncthreads();

    int rA = warpRow + (lane & 15);
    int cAsel = lane >> 4;
    int rB = warpCol + (lane & 7);
    int cBsel = (lane >> 3) & 1;

    int st = 0, pst = 2;
    for (int kt = 0; kt < KT; ++kt) {
        int pf = kt + 2;
        if (pf < KT) {
            cp_tileA(Abase + (size_t)pf * BK, sA + pst * A_TILE);
            cp_tileB(Bbase + (size_t)pf * BK, sB + pst * B_TILE);
            asm volatile("cp.async.commit_group;");
        }
        uint32_t a0 = sA + st * A_TILE;
        uint32_t b0 = sB + st * B_TILE;

        #pragma unroll
        for (int kk = 0; kk < 4; ++kk) {
            uint32_t af[3][4], bf[4][2];
            #pragma unroll
            for (int mt = 0; mt < 3; ++mt) {
                uint32_t addr = a0 + sw128((uint32_t)((rA + mt * 16) * 128
                                                      + (kk * 2 + cAsel) * 16));
                asm volatile("ldmatrix.sync.aligned.m8n8.x4.shared.b16 "
                             "{%0,%1,%2,%3}, [%4];"
                             : "=r"(af[mt][0]), "=r"(af[mt][1]),
                               "=r"(af[mt][2]), "=r"(af[mt][3]) : "r"(addr));
            }
            #pragma unroll
            for (int nt = 0; nt < 4; ++nt) {
                uint32_t addr = b0 + sw128((uint32_t)((rB + nt * 8) * 128
                                                      + (kk * 2 + cBsel) * 16));
                asm volatile("ldmatrix.sync.aligned.m8n8.x2.shared.b16 "
                             "{%0,%1}, [%2];"
                             : "=r"(bf[nt][0]), "=r"(bf[nt][1]) : "r"(addr));
            }
            #pragma unroll
            for (int mt = 0; mt < 3; ++mt)
                #pragma unroll
                for (int nt = 0; nt < 4; ++nt) {
                    asm volatile(
                        "mma.sync.aligned.m16n8k16.row.col.f32.bf16.bf16.f32 "
                        "{%0,%1,%2,%3}, {%4,%5,%6,%7}, {%8,%9}, {%0,%1,%2,%3};"
                        : "+f"(acc[mt][nt][0]), "+f"(acc[mt][nt][1]),
                          "+f"(acc[mt][nt][2]), "+f"(acc[mt][nt][3])
                        : "r"(af[mt][0]), "r"(af[mt][1]),
                          "r"(af[mt][2]), "r"(af[mt][3]),
                          "r"(bf[nt][0]), "r"(bf[nt][1]));
                }
        }
        if (kt + 1 < KT) {
            if (pf < KT) { asm volatile("cp.async.wait_group 1;"); }
            else         { asm volatile("cp.async.wait_group 0;"); }
        }
        __syncthreads();
        st = (st == 2) ? 0 : st + 1;
        pst = (pst == 2) ? 0 : pst + 1;
    }

    float* dst = g_NUM + ((size_t)ks * NB + b) * NQ * NM;
    int rowInTile = lane >> 2;
    int colInTile = (lane & 3) * 2;
    #pragma unroll
    for (int mt = 0; mt < 3; ++mt) {
        #pragma unroll
        for (int nt = 0; nt < 4; ++nt) {
            int qb = q0 + warpRow + mt * 16 + rowInTile;
            int mb = warpCol + nt * 8 + colInTile;
            #pragma unroll
            for (int r = 0; r < 4; ++r) {
                int q = qb + ((r >> 1) ? 8 : 0);
                int m = mb + (r & 1);
                if (q < NQ && m < NM)
                    dst[(size_t)q * NM + m] = acc[mt][nt][r];
            }
        }
    }
}

// ===================== kernel 3: assemble full cost matrix =====================
__global__ void __launch_bounds__(128) k_finalize(const float* __restrict__ logits,
                                                  const float* __restrict__ pboxes,
                                                  const int* __restrict__ glabels,
                                                  const float* __restrict__ gboxes,
                                                  float* __restrict__ out) {
    int q = blockIdx.x, b = blockIdx.y;
    int tid = threadIdx.x;
    __shared__ float probs[NCLS];
    __shared__ float red[128];

    const float* lg = logits + ((size_t)b * NQ + q) * NCLS;
    float x = (tid < NCLS) ? lg[tid] : -3.0e38f;
    red[tid] = x; __syncthreads();
    #pragma unroll
    for (int s = 64; s > 0; s >>= 1) { if (tid < s) red[tid] = fmaxf(red[tid], red[tid + s]); __syncthreads(); }
    float mx = red[0]; __syncthreads();
    float e = (tid < NCLS) ? __expf(x - mx) : 0.f;
    red[tid] = e; __syncthreads();
    #pragma unroll
    for (int s = 64; s > 0; s >>= 1) { if (tid < s) red[tid] += red[tid + s]; __syncthreads(); }
    float inv = 1.f / red[0];
    if (tid < NCLS) probs[tid] = e * inv;
    __syncthreads();

    const float* pb = pboxes + ((size_t)b * NQ + q) * 4;
    float px1 = pb[0], py1 = pb[1], px2 = pb[2], py2 = pb[3];
    float pa = (px2 - px1) * (py2 - py1);
    float psum = g_pm_sum[b * NQ + q];
    const size_t NSTR = (size_t)NB * NQ * NM;

    for (int m = tid; m < NM; m += 128) {
        int lbl = glabels[b * NM + m];
        float cclass = -probs[lbl];
        const float* gb = gboxes + ((size_t)b * NM + m) * 4;
        float gx1 = gb[0], gy1 = gb[1], gx2 = gb[2], gy2 = gb[3];
        float l1 = fabsf(px1 - gx1) + fabsf(py1 - gy1) + fabsf(px2 - gx2) + fabsf(py2 - gy2);
        float iw = fmaxf(fminf(px2, gx2) - fmaxf(px1, gx1), 0.f);
        float ih = fmaxf(fminf(py2, gy2) - fmaxf(py1, gy1), 0.f);
        float inter = iw * ih;
        float ga = (gx2 - gx1) * (gy2 - gy1);
        float uni = pa + ga - inter;
        float iou = inter / (uni + 1e-6f);
        float ew = fmaxf(fmaxf(px2, gx2) - fminf(px1, gx1), 0.f);
        float eh = fmaxf(fmaxf(py2, gy2) - fminf(py1, gy1), 0.f);
        float am = ew * eh;
        float giou = iou - (am - uni) / (am + 1e-6f);
        size_t ni = ((size_t)b * NQ + q) * NM + m;
        float dot = g_NUM[ni] + g_NUM[NSTR + ni] + g_NUM[2 * NSTR + ni] + g_NUM[3 * NSTR + ni];
        float den = psum + g_gm_sum[b * NM + m];
        float cmask = 1.f - (2.f * dot) / (den + 1e-6f);
        out[ni] = cclass + 5.f * (l1 - giou) + 2.f * cmask;
    }
}

// ===================== kernel 4: JV solver (low-sync warp inner loops) =====================
#define HUNG_THREADS 512
#define NQP 301                   // padded cost stride (conflict-free transpose stores)
#define HUNG_SMEM (NM * 4 + NM * NQP * 4 + NQ * 8 + NM * 8 + NM * 4)
#define NSLOT 10

__device__ __forceinline__ uint32_t fkey(float f) {
    uint32_t u = __float_as_uint(f);
    return (u & 0x80000000u) ? ~u : (u | 0x80000000u);
}
__device__ __forceinline__ float funkey(uint32_t k) {
    uint32_t u = (k & 0x80000000u) ? (k & 0x7fffffffu) : ~k;
    return __uint_as_float(u);
}
__device__ __forceinline__ uint32_t redux_min(uint32_t v) {
    uint32_t d;
    asm volatile("redux.sync.min.u32 %0, %1, 0xffffffff;" : "=r"(d) : "r"(v));
    return d;
}

__global__ void __launch_bounds__(HUNG_THREADS) k_hungarian(float* __restrict__ out, int out_size) {
    extern __shared__ char sm[];
    float* u    = reinterpret_cast<float*>(sm);               // [100]
    float* cost = u + NM;                                     // [100][301] transposed
    int* p      = reinterpret_cast<int*>(cost + NM * NQP);    // [300]
    int* way    = p + NQ;                                     // [300]
    int* flA    = way + NQ;                                   // [100]
    int* flB    = flA + NM;                                   // [100]
    int* rowarg = flB + NM;                                   // [100]

    int b = blockIdx.x;
    int tid = threadIdx.x;
    const int lane = tid & 31;
    const int warp = tid >> 5;
    const float* C = out + (size_t)b * NQ * NM;

    for (int idx = tid; idx < NM * NQ; idx += HUNG_THREADS) {
        int q = idx / NM, m = idx - q * NM;
        cost[m * NQP + q] = C[idx];
    }
    for (int j = tid; j < NQ; j += HUNG_THREADS) p[j] = -1;
    __syncthreads();

    // ---- phase 1 (parallel): per-row minima across 16 warps ----
    const bool valid9 = (lane < 12);          // col 288..299 only
    for (int i = warp; i < NM; i += 16) {
        const float* crow = cost + i * NQP;
        float bv = 3.0e38f; int bi = 0x7fffffff;
        #pragma unroll
        for (int s = 0; s < NSLOT; ++s) {
            int col = s * 32 + lane;
            if (s < 9 || valid9) {
                float v = crow[col];
                if (v < bv) { bv = v; bi = col; }
            }
        }
        uint32_t k = fkey(bv);
        uint32_t mk = redux_min(k);
        int jstar = (int)redux_min((k == mk) ? (uint32_t)bi : 0xffffffffu);
        if (lane == 0) { u[i] = funkey(mk); rowarg[i] = jstar; }
    }
    __syncthreads();
    if (tid >= 32) return;

    float vv[NSLOT], minv[NSLOT];
    #pragma unroll
    for (int s = 0; s < NSLOT; ++s) vv[s] = 0.0f;

    // ---- greedy seed (lane-0 scalar bookkeeping) ----
    int nfree = 0;
    if (lane == 0) {
        for (int i = 0; i < NM; ++i) {
            int js = rowarg[i];
            if (p[js] == -1) p[js] = i;
            else flA[nfree++] = i;
        }
    }
    __syncwarp();
    nfree = __shfl_sync(0xffffffffu, nfree, 0);

    // ---- phase 2: augmenting row reduction (<=4 passes) ----
    int* cur = flA; int* nxt = flB;
    for (int pass = 0; pass < 4 && nfree > 0; ++pass) {
        int nnew = 0;
        for (int k = 0; k < nfree; ++k) {
            int i = cur[k];
            for (;;) {
                const float* crow = cost + i * NQP;
                float fv[NSLOT];
                float b1 = 3.0e38f; int c1 = 0x7fffffff;
                #pragma unroll
                for (int s = 0; s < NSLOT; ++s) {
                    int col = s * 32 + lane;
                    float val = 3.0e38f;
                    if (s < 9 || valid9) val = crow[col] - vv[s];
                    fv[s] = val;
                    if (val < b1) { b1 = val; c1 = col; }
                }
                uint32_t k1 = fkey(b1);
                uint32_t u1k = redux_min(k1);
                int j1 = (int)redux_min((k1 == u1k) ? (uint32_t)c1 : 0xffffffffu);
                // second min (exclude column j1)
                float b2 = 3.0e38f; int c2 = 0x7fffffff;
                #pragma unroll
                for (int s = 0; s < NSLOT; ++s) {
                    int col = s * 32 + lane;
                    if (col != j1 && fv[s] < b2) { b2 = fv[s]; c2 = col; }
                }
                uint32_t k2 = fkey(b2);
                uint32_t u2k = redux_min(k2);
                float u1 = funkey(u1k), u2 = funkey(u2k);
                bool strict = (u1 < u2);
                int j2 = 0;
                if (!strict)
                    j2 = (int)redux_min((k2 == u2k) ? (uint32_t)c2 : 0xffffffffu);

                int pack = 0;
                if (lane == 0) {
                    int jt = j1;
                    if (!strict) {
                        int pj1 = p[j1], pj2 = p[j2];
                        if (pj1 != -1 && pj2 == -1) jt = j2;
                    }
                    int ev = p[jt];
                    u[i] = u2; p[jt] = i;
                    pack = (jt << 9) | (ev + 1);
                }
                pack = __shfl_sync(0xffffffffu, pack, 0);
                int jt = pack >> 9;
                int ev = (pack & 511) - 1;
                if (strict && lane == (jt & 31)) vv[jt >> 5] -= (u2 - u1);

                if (ev == -1) break;
                if (strict) { i = ev; continue; }
                if (lane == 0) nxt[nnew] = ev;
                ++nnew;
                break;
            }
        }
        __syncwarp();
        int* t = cur; cur = nxt; nxt = t;
        nfree = nnew;
    }

    // ---- phase 3: shortest augmenting path for the remainder ----
    for (int fidx = 0; fidx < nfree; ++fidx) {
        int i = cur[fidx];
        unsigned usedmask = 0;
        #pragma unroll
        for (int s = 0; s < NSLOT; ++s) minv[s] = 3.0e38f;
        int cr = i, j0 = -1;

        while (true) {
            float ucr = u[cr];
            const float* crow = cost + cr * NQP;
            float bv = 3.0e38f; int bi = 0x7fffffff;
            #pragma unroll
            for (int s = 0; s < NSLOT; ++s) {
                int col = s * 32 + lane;
                bool ok = (s < 9 || valid9) && !((usedmask >> s) & 1u);
                if (ok) {
                    float cv = crow[col] - ucr - vv[s];
                    if (cv < minv[s]) { minv[s] = cv; way[col] = j0; }
                    if (minv[s] < bv) { bv = minv[s]; bi = col; }
                }
            }
            uint32_t k = fkey(bv);
            uint32_t mk = redux_min(k);
            float delta = funkey(mk);
            int j1 = (int)redux_min((k == mk) ? (uint32_t)bi : 0xffffffffu);

            #pragma unroll
            for (int s = 0; s < NSLOT; ++s) {
                int col = s * 32 + lane;
                if (s < 9 || valid9) {
                    if ((usedmask >> s) & 1u) {
                        u[p[col]] += delta;
                        vv[s] -= delta;
                    } else {
                        minv[s] -= delta;
                    }
                }
            }
            if (lane == 0) u[i] += delta;
            if (lane == (j1 & 31)) usedmask |= 1u << (j1 >> 5);
            j0 = j1;
            cr = p[j1];
            __syncwarp();
            if (cr == -1) break;
        }

        if (lane == 0) {
            int j = j0;
            while (j != -1) {
                int jp = way[j];
                p[j] = (jp != -1) ? p[jp] : i;
                j = jp;
            }
        }
        __syncwarp();
    }

    // ---- output: parallel compaction (ballot prefix ranks) ----
    if (out_size >= NB * NQ * NM + 2 * NB * NM) {
        float* pi = out + (size_t)NB * NQ * NM + (size_t)b * NM;
        float* gi = pi + (size_t)NB * NM;
        int base = 0;
        #pragma unroll
        for (int blk0 = 0; blk0 < NQ; blk0 += 32) {
            int col = blk0 + lane;
            int pv = (col < NQ) ? p[col] : -1;
            unsigned mask = __ballot_sync(0xffffffffu, pv >= 0);
            if (pv >= 0) {
                int r = base + __popc(mask & ((1u << lane) - 1u));
                pi[r] = (float)col;
                gi[r] = (float)pv;
            }
            base += __popc(mask);
        }
    }
}

// ===================== launch =====================
extern "C" void kernel_launch(void* const* d_in, const int* in_sizes, int n_in,
                              void* d_out, int out_size) {
    const float* pred_logits = (const float*)d_in[0];
    const float* pred_boxes  = (const float*)d_in[1];
    const float* pred_masks  = (const float*)d_in[2];
    const int*   gt_labels   = (const int*)d_in[3];
    const float* gt_boxes    = (const float*)d_in[4];
    const float* gt_masks    = (const float*)d_in[5];
    float* out = (float*)d_out;

    k_convert<<<NB * NQ + NB * NM, 256>>>(pred_masks, gt_masks);

    cudaFuncSetAttribute(k_mask_gemm, cudaFuncAttributeMaxDynamicSharedMemorySize, GEMM_SMEM);
    k_mask_gemm<<<dim3(NQT, NB, KSPLIT), 256, GEMM_SMEM>>>();

    k_finalize<<<dim3(NQ, NB), 128>>>(pred_logits, pred_boxes, gt_labels, gt_boxes, out);

    cudaFuncSetAttribute(k_hungarian, cudaFuncAttributeMaxDynamicSharedMemorySize, HUNG_SMEM);
    k_hungarian<<<NB, HUNG_THREADS, HUNG_SMEM>>>(out, out_size);
}